// round 12
// baseline (speedup 1.0000x reference)
#include <cuda_runtime.h>
#include <math.h>
#include <stdint.h>

// Problem constants (fixed by setup_inputs)
#define BATCH   2
#define IMG     224
#define TOKENS  (BATCH*IMG*IMG)   // 100352
#define DIM     768
#define NH      12
#define HD      64
#define WS      7
#define L       (WS*WS)           // 49
#define NWIN    (BATCH*(IMG/WS)*(IMG/WS))  // 2048
#define SHIFT   3

// Scratch (device globals: allocation is forbidden in kernel_launch)
__device__ float    g_qkv[(size_t)TOKENS * 3 * DIM];
__device__ uint16_t g_xhi[(size_t)TOKENS * DIM];
__device__ uint16_t g_xlo[(size_t)TOKENS * DIM];
__device__ uint16_t g_qwhi[(size_t)3 * DIM * DIM];
__device__ uint16_t g_qwlo[(size_t)3 * DIM * DIM];
__device__ uint16_t g_pwhi[(size_t)DIM * DIM];
__device__ uint16_t g_pwlo[(size_t)DIM * DIM];
__device__ uint16_t g_atthi[(size_t)TOKENS * DIM];
__device__ uint16_t g_attlo[(size_t)TOKENS * DIM];
__device__ float    g_sin[L * 32];
__device__ float    g_cos[L * 32];

// ============================================================================
// helpers
// ============================================================================
__device__ __forceinline__ uint32_t smem_u32(const void* p) {
    uint32_t a;
    asm("{ .reg .u64 t; cvta.to.shared.u64 t, %1; cvt.u32.u64 %0, t; }" : "=r"(a) : "l"(p));
    return a;
}

__device__ __forceinline__ void split_pack(float x, float y, uint32_t& hi, uint32_t& lo) {
    asm("cvt.rn.bf16x2.f32 %0, %1, %2;" : "=r"(hi) : "f"(y), "f"(x));
    float hx = __uint_as_float(hi << 16);
    float hy = __uint_as_float(hi & 0xffff0000u);
    float lx = x - hx;
    float ly = y - hy;
    asm("cvt.rn.bf16x2.f32 %0, %1, %2;" : "=r"(lo) : "f"(ly), "f"(lx));
}

__device__ __forceinline__ void split1(float x, uint16_t& h, uint16_t& l) {
    uint16_t hh;
    asm("cvt.rn.bf16.f32 %0, %1;" : "=h"(hh) : "f"(x));
    float hf = __uint_as_float(((uint32_t)hh) << 16);
    asm("cvt.rn.bf16.f32 %0, %1;" : "=h"(l) : "f"(x - hf));
    h = hh;
}

// ---- packed f32x2 (Blackwell FFMA2) ----
__device__ __forceinline__ unsigned long long pk2(float x, float y) {
    unsigned long long r;
    asm("mov.b64 %0, {%1,%2};" : "=l"(r) : "f"(x), "f"(y));
    return r;
}
__device__ __forceinline__ void fma2(unsigned long long& d,
                                     unsigned long long a, unsigned long long b) {
    asm("fma.rn.f32x2 %0, %1, %2, %0;" : "+l"(d) : "l"(a), "l"(b));
}
__device__ __forceinline__ float2 upk2(unsigned long long v) {
    float x, y;
    asm("mov.b64 {%0,%1}, %2;" : "=f"(x), "=f"(y) : "l"(v));
    return make_float2(x, y);
}

#define CPA16(dst, src) \
    asm volatile("cp.async.cg.shared.global [%0], [%1], 16;" :: "r"(dst), "l"(src) : "memory")
#define CPA_COMMIT() asm volatile("cp.async.commit_group;" ::: "memory")
#define CPA_WAIT2()  asm volatile("cp.async.wait_group 2;" ::: "memory")

#define LDSM4(r, addr) \
    asm volatile("ldmatrix.sync.aligned.m8n8.x4.shared.b16 {%0,%1,%2,%3}, [%4];" \
        : "=r"((r)[0]), "=r"((r)[1]), "=r"((r)[2]), "=r"((r)[3]) : "r"(addr))

#define MMA16816(d, a, b0, b1) \
    asm volatile("mma.sync.aligned.m16n8k16.row.col.f32.bf16.bf16.f32 " \
        "{%0,%1,%2,%3},{%4,%5,%6,%7},{%8,%9},{%0,%1,%2,%3};" \
        : "+f"((d)[0]), "+f"((d)[1]), "+f"((d)[2]), "+f"((d)[3]) \
        : "r"((a)[0]), "r"((a)[1]), "r"((a)[2]), "r"((a)[3]), "r"(b0), "r"(b1))

// ============================================================================
// fp32 -> bf16 hi/lo split pre-pass (optionally also builds RoPE tables)
// ============================================================================
__global__ void split_kernel(const float* __restrict__ src,
                             uint16_t* __restrict__ hi, uint16_t* __restrict__ lo,
                             size_t n4, int do_rope)
{
    if (do_rope && blockIdx.x == 0) {
        for (int i = threadIdx.x; i < L * 32; i += blockDim.x) {
            int tok = i >> 5, d = i & 31;
            int ty = tok / WS, tx = tok - ty * WS;
            int f = d & 15;
            float inv = powf(100.0f, -((float)f) / 16.0f);
            float ang = ((d < 16) ? (float)ty : (float)tx) * inv;
            g_sin[i] = sinf(ang);
            g_cos[i] = cosf(ang);
        }
    }
    size_t idx = (size_t)blockIdx.x * blockDim.x + threadIdx.x;
    size_t stride = (size_t)gridDim.x * blockDim.x;
    for (; idx < n4; idx += stride) {
        float4 v = ((const float4*)src)[idx];
        uint32_t h0, l0, h1, l1;
        split_pack(v.x, v.y, h0, l0);
        split_pack(v.z, v.w, h1, l1);
        ((uint2*)hi)[idx] = make_uint2(h0, h1);
        ((uint2*)lo)[idx] = make_uint2(l0, l1);
    }
}

// ============================================================================
// 3x-BF16-split GEMM:  C[M,N] = A[M,K] @ W[N,K]^T  (fp32 out)
// CTA tile 128x128, 128 threads (4 warps, 2m x 2n, warp tile 64x64),
// BK=16, cp.async 4-stage, 2 CTAs/SM (256 threads/SM -> 256-reg budget).
// Crossbar load: 85 B/MMA (33%), L2: 21 B/cyc/SM. Tensor-issue-bound.
// Requires M%128==0, N%128==0, K%16==0.
// ============================================================================
#define BM 128
#define BN 128
#define BK 16
#define PADB 48
#define A_LO  6144u               // 128*48
#define B_HI  12288u
#define B_LO  18432u
#define BUF_B 24576u
#define STAGES 4
#define SMEM_GEMM (STAGES * BUF_B)   // 98304

__global__ __launch_bounds__(128, 2) void gemm_presplit_kernel(
    const uint16_t* __restrict__ Ahi, const uint16_t* __restrict__ Alo,
    const uint16_t* __restrict__ Bhi, const uint16_t* __restrict__ Blo,
    float* __restrict__ C, int M, int N, int K)
{
    extern __shared__ char smem[];
    const uint32_t sb = smem_u32(smem);
    const int tid  = threadIdx.x;
    const int lane = tid & 31;
    const int wid  = tid >> 5;
    const int mtile = blockIdx.y, ntile = blockIdx.x;
    const int rm = (wid & 1) * 64;    // 2 m-warps
    const int nb = (wid >> 1) * 64;   // 2 n-warps

    // cp.async: thread t -> row t of each tile, 32B per row (2x16B chunks)
    const int row = tid;
    const uint16_t* pAhi = Ahi + (size_t)(mtile * BM + row) * K;
    const uint16_t* pAlo = Alo + (size_t)(mtile * BM + row) * K;
    const uint16_t* pBhi = Bhi + (size_t)(ntile * BN + row) * K;
    const uint16_t* pBlo = Blo + (size_t)(ntile * BN + row) * K;

    const uint32_t dA = sb + (uint32_t)(row * PADB);
    const uint32_t dB = sb + B_HI + (uint32_t)(row * PADB);

    auto issue = [&](int s) {
        const uint32_t off = (uint32_t)(s & 3) * BUF_B;
        const int k0 = s * BK;
        CPA16(dA + off,                      pAhi + k0);
        CPA16(dA + off + 16,                 pAhi + k0 + 8);
        CPA16(dA + off + A_LO,               pAlo + k0);
        CPA16(dA + off + A_LO + 16,          pAlo + k0 + 8);
        CPA16(dB + off,                      pBhi + k0);
        CPA16(dB + off + 16,                 pBhi + k0 + 8);
        CPA16(dB + off + (B_LO - B_HI),      pBlo + k0);
        CPA16(dB + off + (B_LO - B_HI) + 16, pBlo + k0 + 8);
        CPA_COMMIT();
    };

    float acc[4][8][4];
#pragma unroll
    for (int mt = 0; mt < 4; ++mt)
#pragma unroll
        for (int nt = 0; nt < 8; ++nt)
#pragma unroll
            for (int e = 0; e < 4; ++e) acc[mt][nt][e] = 0.0f;

    const uint32_t a_l = sb + (uint32_t)((rm + (lane & 15)) * PADB + (lane >> 4) * 16);
    const uint32_t b_l = sb + B_HI + (uint32_t)((nb + (lane & 7) + ((lane >> 4) << 3)) * PADB
                                                + ((lane >> 3) & 1) * 16);

    const int NIT = K / BK;   // 48
    issue(0); issue(1); issue(2);

    for (int it = 0; it < NIT; ++it) {
        CPA_WAIT2();          // stage 'it' landed (<=2 groups younger remain)
        __syncthreads();
        if (it + 3 < NIT) issue(it + 3);   // refills stage (it-1)%4: safe post-barrier
        else CPA_COMMIT();                 // empty group keeps wait counts uniform

        const uint32_t so = (uint32_t)(it & 3) * BUF_B;

        // all fragments up front: A 8x LDSM4, B 8x LDSM4 (64 frag regs)
        uint32_t ah[4][4], al[4][4], bh[4][4], bl[4][4];
#pragma unroll
        for (int mt = 0; mt < 4; ++mt) {
            LDSM4(ah[mt], a_l + so + mt * (16 * PADB));
            LDSM4(al[mt], a_l + so + A_LO + mt * (16 * PADB));
        }
#pragma unroll
        for (int nt2 = 0; nt2 < 4; ++nt2) {
            LDSM4(bh[nt2], b_l + so + nt2 * (16 * PADB));
            LDSM4(bl[nt2], b_l + so + (B_LO - B_HI) + nt2 * (16 * PADB));
        }

        // term-major: 32-MMA reuse distance per accumulator
#pragma unroll
        for (int mt = 0; mt < 4; ++mt)
#pragma unroll
            for (int nt2 = 0; nt2 < 4; ++nt2) {
                MMA16816(acc[mt][2 * nt2],     ah[mt], bh[nt2][0], bh[nt2][1]);
                MMA16816(acc[mt][2 * nt2 + 1], ah[mt], bh[nt2][2], bh[nt2][3]);
            }
#pragma unroll
        for (int mt = 0; mt < 4; ++mt)
#pragma unroll
            for (int nt2 = 0; nt2 < 4; ++nt2) {
                MMA16816(acc[mt][2 * nt2],     ah[mt], bl[nt2][0], bl[nt2][1]);
                MMA16816(acc[mt][2 * nt2 + 1], ah[mt], bl[nt2][2], bl[nt2][3]);
            }
#pragma unroll
        for (int mt = 0; mt < 4; ++mt)
#pragma unroll
            for (int nt2 = 0; nt2 < 4; ++nt2) {
                MMA16816(acc[mt][2 * nt2],     al[mt], bh[nt2][0], bh[nt2][1]);
                MMA16816(acc[mt][2 * nt2 + 1], al[mt], bh[nt2][2], bh[nt2][3]);
            }
    }

    // ---- epilogue ----
    const int rowb = mtile * BM + rm + (lane >> 2);
    const int colb = ntile * BN + nb + (lane & 3) * 2;
#pragma unroll
    for (int mt = 0; mt < 4; ++mt) {
#pragma unroll
        for (int nt = 0; nt < 8; ++nt) {
            float* p = C + (size_t)(rowb + mt * 16) * N + colb + nt * 8;
            *(float2*)p                   = make_float2(acc[mt][nt][0], acc[mt][nt][1]);
            *(float2*)(p + 8 * (size_t)N) = make_float2(acc[mt][nt][2], acc[mt][nt][3]);
        }
    }
}

// ============================================================================
// Window attention: one block per (head, window), 128 threads. (unchanged)
// ============================================================================
__global__ __launch_bounds__(128) void window_attn_kernel(
    const float* __restrict__ qkv,
    uint16_t* __restrict__ atthi, uint16_t* __restrict__ attlo)
{
    __shared__ __align__(16) float Qs[L * 68];
    __shared__ __align__(16) float Ks[L * 68];
    __shared__ __align__(16) float Vs[L * 64];
    __shared__ float S[L * 52];
    __shared__ float qn[L], kn[L];
    __shared__ int grows[L];

    const int h   = blockIdx.x;
    const int w   = blockIdx.y;
    const int tid = threadIdx.x;
    const int lane = tid & 31;
    const int warp = tid >> 5;
    const int b   = w >> 10;
    const int rem = w & 1023;
    const int wh  = rem >> 5, ww = rem & 31;

    if (tid < L) {
        int ty = tid / WS, tx = tid - ty * WS;
        int y = wh * WS + ty + SHIFT; if (y >= IMG) y -= IMG;
        int x = ww * WS + tx + SHIFT; if (x >= IMG) x -= IMG;
        grows[tid] = b * (IMG * IMG) + y * IMG + x;
    }
    __syncthreads();

    for (int r = warp; r < 3 * L; r += 4) {
        int kind = r / L;
        int rw   = r - kind * L;
        size_t base = (size_t)grows[rw] * (3 * DIM) + h * HD + (size_t)kind * DIM;
        float t1 = qkv[base + lane];
        float t2 = qkv[base + lane + 32];
        if (kind == 2) {
            Vs[rw * 64 + lane]      = t1;
            Vs[rw * 64 + lane + 32] = t2;
        } else {
            float s = g_sin[rw * 32 + lane];
            float c = g_cos[rw * 32 + lane];
            float r1 = t1 * c - t2 * s;
            float r2 = t1 * s + t2 * c;
            float* dst = (kind == 0) ? Qs : Ks;
            dst[rw * 68 + lane]      = r1;
            dst[rw * 68 + lane + 32] = r2;
        }
    }
    __syncthreads();

    if (tid < L) {
        float ssq = 0.0f;
#pragma unroll
        for (int d4 = 0; d4 < 16; ++d4) {
            float4 v = *(const float4*)&Ks[tid * 68 + d4 * 4];
            ssq += v.x * v.x + v.y * v.y + v.z * v.z + v.w * v.w;
        }
        kn[tid] = 1.0f / fmaxf(sqrtf(ssq), 1e-12f);
    } else if (tid >= 64 && tid < 64 + L) {
        int i = tid - 64;
        float ssq = 0.0f;
#pragma unroll
        for (int d4 = 0; d4 < 16; ++d4) {
            float4 v = *(const float4*)&Qs[i * 68 + d4 * 4];
            ssq += v.x * v.x + v.y * v.y + v.z * v.z + v.w * v.w;
        }
        qn[i] = 100.0f / fmaxf(sqrtf(ssq), 1e-12f);
    }
    __syncthreads();

    if (tid < 2 * L) {
        int g = (tid >= L) ? 1 : 0;
        int i = tid - g * L;
        unsigned long long qp[32];
#pragma unroll
        for (int d4 = 0; d4 < 16; ++d4) {
            float4 v = *(const float4*)&Qs[i * 68 + d4 * 4];
            qp[d4 * 2]     = pk2(v.x, v.y);
            qp[d4 * 2 + 1] = pk2(v.z, v.w);
        }
        float qs = qn[i];
        int j0 = g ? 25 : 0, j1 = g ? L : 25;
        for (int j = j0; j < j1; ++j) {
            unsigned long long a0 = 0, a1 = 0, a2 = 0, a3 = 0;
#pragma unroll
            for (int d4 = 0; d4 < 8; ++d4) {
                float4 k0 = *(const float4*)&Ks[j * 68 + d4 * 8];
                float4 k1 = *(const float4*)&Ks[j * 68 + d4 * 8 + 4];
                fma2(a0, qp[d4 * 4],     pk2(k0.x, k0.y));
                fma2(a1, qp[d4 * 4 + 1], pk2(k0.z, k0.w));
                fma2(a2, qp[d4 * 4 + 2], pk2(k1.x, k1.y));
                fma2(a3, qp[d4 * 4 + 3], pk2(k1.z, k1.w));
            }
            float2 r0 = upk2(a0), r1 = upk2(a1), r2 = upk2(a2), r3 = upk2(a3);
            float dot = (r0.x + r0.y) + (r1.x + r1.y) + (r2.x + r2.y) + (r3.x + r3.y);
            S[i * 52 + j] = dot * (qs * kn[j]);
        }
    }
    __syncthreads();

    if (tid < L) {
        float mx = -1e30f;
        for (int j = 0; j < L; ++j) mx = fmaxf(mx, S[tid * 52 + j]);
        float sum = 0.0f;
        for (int j = 0; j < L; ++j) {
            float e = __expf(S[tid * 52 + j] - mx);
            S[tid * 52 + j] = e;
            sum += e;
        }
        float inv = 1.0f / sum;
        for (int j = 0; j < L; ++j) S[tid * 52 + j] *= inv;
    }
    __syncthreads();

    if (tid < 2 * L) {
        int g = (tid >= L) ? 1 : 0;
        int i = tid - g * L;
        unsigned long long ov[16];
#pragma unroll
        for (int d = 0; d < 16; ++d) ov[d] = 0ull;
        for (int j = 0; j < L; ++j) {
            float wgt = S[i * 52 + j];
            unsigned long long wp = pk2(wgt, wgt);
#pragma unroll
            for (int d4 = 0; d4 < 4; ++d4) {
                float4 v0 = *(const float4*)&Vs[j * 64 + g * 32 + d4 * 8];
                float4 v1 = *(const float4*)&Vs[j * 64 + g * 32 + d4 * 8 + 4];
                fma2(ov[d4 * 4],     wp, pk2(v0.x, v0.y));
                fma2(ov[d4 * 4 + 1], wp, pk2(v0.z, v0.w));
                fma2(ov[d4 * 4 + 2], wp, pk2(v1.x, v1.y));
                fma2(ov[d4 * 4 + 3], wp, pk2(v1.z, v1.w));
            }
        }
#pragma unroll
        for (int d = 0; d < 16; ++d) {
            float2 r = upk2(ov[d]);
            Qs[i * 68 + g * 32 + d * 2]     = r.x;
            Qs[i * 68 + g * 32 + d * 2 + 1] = r.y;
        }
    }
    __syncthreads();

    for (int t = warp; t < L; t += 4) {
        size_t o = (size_t)grows[t] * DIM + h * HD;
        float v0 = Qs[t * 68 + lane];
        float v1 = Qs[t * 68 + lane + 32];
        uint16_t h0, l0, h1, l1;
        split1(v0, h0, l0);
        split1(v1, h1, l1);
        atthi[o + lane]      = h0;
        attlo[o + lane]      = l0;
        atthi[o + lane + 32] = h1;
        attlo[o + lane + 32] = l1;
    }
}

// ---------------------------------------------------------------------------
extern "C" void kernel_launch(void* const* d_in, const int* in_sizes, int n_in,
                              void* d_out, int out_size)
{
    const float* x     = (const float*)d_in[0];
    const float* qkv_w = (const float*)d_in[1];
    const float* projw = (const float*)d_in[2];
    float* out = (float*)d_out;

    float *qkv_ptr;
    uint16_t *xhi, *xlo, *qwhi, *qwlo, *pwhi, *pwlo, *atthi, *attlo;
    cudaGetSymbolAddress((void**)&qkv_ptr, g_qkv);
    cudaGetSymbolAddress((void**)&xhi,  g_xhi);
    cudaGetSymbolAddress((void**)&xlo,  g_xlo);
    cudaGetSymbolAddress((void**)&qwhi, g_qwhi);
    cudaGetSymbolAddress((void**)&qwlo, g_qwlo);
    cudaGetSymbolAddress((void**)&pwhi, g_pwhi);
    cudaGetSymbolAddress((void**)&pwlo, g_pwlo);
    cudaGetSymbolAddress((void**)&atthi, g_atthi);
    cudaGetSymbolAddress((void**)&attlo, g_attlo);

    cudaFuncSetAttribute(gemm_presplit_kernel,
                         cudaFuncAttributeMaxDynamicSharedMemorySize, SMEM_GEMM);

    // Launch order: qkv GEMM is launch #4 (the profiled slot).
    split_kernel<<<1024, 256>>>(x, xhi, xlo, (size_t)TOKENS * DIM / 4, 1);      // 1 (+rope)
    split_kernel<<<64, 256>>>(qkv_w, qwhi, qwlo, (size_t)3 * DIM * DIM / 4, 0); // 2
    split_kernel<<<32, 256>>>(projw, pwhi, pwlo, (size_t)DIM * DIM / 4, 0);     // 3

    // qkv = x @ qkv_w^T : M=100352, N=2304, K=768                               // 4 <-- profiled
    gemm_presplit_kernel<<<dim3(3 * DIM / BN, TOKENS / BM), 128, SMEM_GEMM>>>(
        xhi, xlo, qwhi, qwlo, qkv_ptr, TOKENS, 3 * DIM, DIM);

    // windowed attention (writes bf16 hi/lo att)                               // 5
    window_attn_kernel<<<dim3(NH, NWIN), 128>>>(qkv_ptr, atthi, attlo);

    // out = att @ proj_w^T : M=100352, N=768, K=768                             // 6
    gemm_presplit_kernel<<<dim3(DIM / BN, TOKENS / BM), 128, SMEM_GEMM>>>(
        atthi, attlo, pwhi, pwlo, out, TOKENS, DIM, DIM);
}

// round 13
// speedup vs baseline: 1.3345x; 1.3345x over previous
#include <cuda_runtime.h>
#include <math.h>
#include <stdint.h>

// Problem constants (fixed by setup_inputs)
#define BATCH   2
#define IMG     224
#define TOKENS  (BATCH*IMG*IMG)   // 100352
#define DIM     768
#define NH      12
#define HD      64
#define WS      7
#define L       (WS*WS)           // 49
#define NWIN    (BATCH*(IMG/WS)*(IMG/WS))  // 2048
#define SHIFT   3

// Scratch (device globals: allocation is forbidden in kernel_launch)
__device__ float    g_qkv[(size_t)TOKENS * 3 * DIM];
__device__ uint16_t g_xhi[(size_t)TOKENS * DIM];
__device__ uint16_t g_xlo[(size_t)TOKENS * DIM];
__device__ uint16_t g_qwhi[(size_t)3 * DIM * DIM];
__device__ uint16_t g_qwlo[(size_t)3 * DIM * DIM];
__device__ uint16_t g_pwhi[(size_t)DIM * DIM];
__device__ uint16_t g_pwlo[(size_t)DIM * DIM];
__device__ uint16_t g_atthi[(size_t)TOKENS * DIM];
__device__ uint16_t g_attlo[(size_t)TOKENS * DIM];
__device__ float    g_sin[L * 32];
__device__ float    g_cos[L * 32];

// ============================================================================
// helpers
// ============================================================================
__device__ __forceinline__ uint32_t smem_u32(const void* p) {
    uint32_t a;
    asm("{ .reg .u64 t; cvta.to.shared.u64 t, %1; cvt.u32.u64 %0, t; }" : "=r"(a) : "l"(p));
    return a;
}

__device__ __forceinline__ void split_pack(float x, float y, uint32_t& hi, uint32_t& lo) {
    asm("cvt.rn.bf16x2.f32 %0, %1, %2;" : "=r"(hi) : "f"(y), "f"(x));
    float hx = __uint_as_float(hi << 16);
    float hy = __uint_as_float(hi & 0xffff0000u);
    float lx = x - hx;
    float ly = y - hy;
    asm("cvt.rn.bf16x2.f32 %0, %1, %2;" : "=r"(lo) : "f"(ly), "f"(lx));
}

__device__ __forceinline__ void split1(float x, uint16_t& h, uint16_t& l) {
    uint16_t hh;
    asm("cvt.rn.bf16.f32 %0, %1;" : "=h"(hh) : "f"(x));
    float hf = __uint_as_float(((uint32_t)hh) << 16);
    asm("cvt.rn.bf16.f32 %0, %1;" : "=h"(l) : "f"(x - hf));
    h = hh;
}

// ---- packed f32x2 (Blackwell FFMA2) ----
__device__ __forceinline__ unsigned long long pk2(float x, float y) {
    unsigned long long r;
    asm("mov.b64 %0, {%1,%2};" : "=l"(r) : "f"(x), "f"(y));
    return r;
}
__device__ __forceinline__ void fma2(unsigned long long& d,
                                     unsigned long long a, unsigned long long b) {
    asm("fma.rn.f32x2 %0, %1, %2, %0;" : "+l"(d) : "l"(a), "l"(b));
}
__device__ __forceinline__ float2 upk2(unsigned long long v) {
    float x, y;
    asm("mov.b64 {%0,%1}, %2;" : "=f"(x), "=f"(y) : "l"(v));
    return make_float2(x, y);
}

#define CPA16(dst, src) \
    asm volatile("cp.async.cg.shared.global [%0], [%1], 16;" :: "r"(dst), "l"(src) : "memory")
#define CPA_COMMIT()  asm volatile("cp.async.commit_group;" ::: "memory")
#define CPA_WAIT2()   asm volatile("cp.async.wait_group 2;" ::: "memory")
#define CPA_WAITALL() asm volatile("cp.async.wait_all;" ::: "memory")

#define LDSM4(r, addr) \
    asm volatile("ldmatrix.sync.aligned.m8n8.x4.shared.b16 {%0,%1,%2,%3}, [%4];" \
        : "=r"((r)[0]), "=r"((r)[1]), "=r"((r)[2]), "=r"((r)[3]) : "r"(addr))

#define MMA16816(d, a, b0, b1) \
    asm volatile("mma.sync.aligned.m16n8k16.row.col.f32.bf16.bf16.f32 " \
        "{%0,%1,%2,%3},{%4,%5,%6,%7},{%8,%9},{%0,%1,%2,%3};" \
        : "+f"((d)[0]), "+f"((d)[1]), "+f"((d)[2]), "+f"((d)[3]) \
        : "r"((a)[0]), "r"((a)[1]), "r"((a)[2]), "r"((a)[3]), "r"(b0), "r"(b1))

// ============================================================================
// fp32 -> bf16 hi/lo split pre-pass (optionally also builds RoPE tables)
// ============================================================================
__global__ void split_kernel(const float* __restrict__ src,
                             uint16_t* __restrict__ hi, uint16_t* __restrict__ lo,
                             size_t n4, int do_rope)
{
    if (do_rope && blockIdx.x == 0) {
        for (int i = threadIdx.x; i < L * 32; i += blockDim.x) {
            int tok = i >> 5, d = i & 31;
            int ty = tok / WS, tx = tok - ty * WS;
            int f = d & 15;
            float inv = powf(100.0f, -((float)f) / 16.0f);
            float ang = ((d < 16) ? (float)ty : (float)tx) * inv;
            g_sin[i] = sinf(ang);
            g_cos[i] = cosf(ang);
        }
    }
    size_t idx = (size_t)blockIdx.x * blockDim.x + threadIdx.x;
    size_t stride = (size_t)gridDim.x * blockDim.x;
    for (; idx < n4; idx += stride) {
        float4 v = ((const float4*)src)[idx];
        uint32_t h0, l0, h1, l1;
        split_pack(v.x, v.y, h0, l0);
        split_pack(v.z, v.w, h1, l1);
        ((uint2*)hi)[idx] = make_uint2(h0, h1);
        ((uint2*)lo)[idx] = make_uint2(l0, l1);
    }
}

// ============================================================================
// 3x-BF16-split GEMM (R8 configuration — empirical best):
//   C[M,N] = A[M,K] @ W[N,K]^T  (fp32 out)
// CTA tile 128x128, BK=16, 256 threads (8 warps, 4m x 2n, warp tile 32x64),
// cp.async 4-stage, 2 CTAs/SM. Requires M%128==0, N%128==0, K%16==0.
// ============================================================================
#define BM 128
#define BN 128
#define BK 16
#define PADB 48
#define A_LO  6144u
#define B_HI  12288u
#define B_LO  18432u
#define BUF_B 24576u
#define STAGES 4
#define SMEM_GEMM (STAGES * BUF_B)   // 98304

__global__ __launch_bounds__(256, 2) void gemm_presplit_kernel(
    const uint16_t* __restrict__ Ahi, const uint16_t* __restrict__ Alo,
    const uint16_t* __restrict__ Bhi, const uint16_t* __restrict__ Blo,
    float* __restrict__ C, int M, int N, int K)
{
    extern __shared__ char smem[];
    const uint32_t sb = smem_u32(smem);
    const int tid  = threadIdx.x;
    const int lane = tid & 31;
    const int wid  = tid >> 5;
    const int mtile = blockIdx.y, ntile = blockIdx.x;
    const int rm = (wid & 3) * 32;    // 4 m-warps
    const int nb = (wid >> 2) * 64;   // 2 n-warps

    const int row = tid >> 1, half = tid & 1;
    const uint16_t* pAhi = Ahi + (size_t)(mtile * BM + row) * K + half * 8;
    const uint16_t* pAlo = Alo + (size_t)(mtile * BM + row) * K + half * 8;
    const uint16_t* pBhi = Bhi + (size_t)(ntile * BN + row) * K + half * 8;
    const uint16_t* pBlo = Blo + (size_t)(ntile * BN + row) * K + half * 8;

    const uint32_t dA = sb + (uint32_t)(row * PADB + half * 16);
    const uint32_t dB = sb + B_HI + (uint32_t)(row * PADB + half * 16);

    auto issue = [&](int s) {
        const uint32_t off = (uint32_t)(s & 3) * BUF_B;
        const int k0 = s * BK;
        CPA16(dA + off,                 pAhi + k0);
        CPA16(dA + off + A_LO,          pAlo + k0);
        CPA16(dB + off,                 pBhi + k0);
        CPA16(dB + off + (B_LO - B_HI), pBlo + k0);
        CPA_COMMIT();
    };

    float acc[2][8][4];
#pragma unroll
    for (int mt = 0; mt < 2; ++mt)
#pragma unroll
        for (int nt = 0; nt < 8; ++nt)
#pragma unroll
            for (int e = 0; e < 4; ++e) acc[mt][nt][e] = 0.0f;

    const uint32_t a_l = sb + (uint32_t)((rm + (lane & 15)) * PADB + (lane >> 4) * 16);
    const uint32_t b_l = sb + B_HI + (uint32_t)((nb + (lane & 7) + ((lane >> 4) << 3)) * PADB
                                                + ((lane >> 3) & 1) * 16);

    const int NIT = K / BK;   // 48
    issue(0); issue(1); issue(2);

    for (int it = 0; it < NIT; ++it) {
        CPA_WAIT2();
        __syncthreads();
        const uint32_t so = (uint32_t)(it & 3) * BUF_B;

        uint32_t ah[2][4], al[2][4];
#pragma unroll
        for (int mt = 0; mt < 2; ++mt) {
            LDSM4(ah[mt], a_l + so + mt * (16 * PADB));
            LDSM4(al[mt], a_l + so + A_LO + mt * (16 * PADB));
        }

#pragma unroll
        for (int hf = 0; hf < 2; ++hf) {
            uint32_t bh[2][4], bl[2][4];
#pragma unroll
            for (int q = 0; q < 2; ++q) {
                const int nt2 = hf * 2 + q;
                LDSM4(bh[q], b_l + so + nt2 * (16 * PADB));
                LDSM4(bl[q], b_l + so + (B_LO - B_HI) + nt2 * (16 * PADB));
            }
#pragma unroll
            for (int mt = 0; mt < 2; ++mt)
#pragma unroll
                for (int q = 0; q < 2; ++q) {
                    MMA16816(acc[mt][hf * 4 + 2 * q],     ah[mt], bh[q][0], bh[q][1]);
                    MMA16816(acc[mt][hf * 4 + 2 * q + 1], ah[mt], bh[q][2], bh[q][3]);
                }
#pragma unroll
            for (int mt = 0; mt < 2; ++mt)
#pragma unroll
                for (int q = 0; q < 2; ++q) {
                    MMA16816(acc[mt][hf * 4 + 2 * q],     ah[mt], bl[q][0], bl[q][1]);
                    MMA16816(acc[mt][hf * 4 + 2 * q + 1], ah[mt], bl[q][2], bl[q][3]);
                }
#pragma unroll
            for (int mt = 0; mt < 2; ++mt)
#pragma unroll
                for (int q = 0; q < 2; ++q) {
                    MMA16816(acc[mt][hf * 4 + 2 * q],     al[mt], bh[q][0], bh[q][1]);
                    MMA16816(acc[mt][hf * 4 + 2 * q + 1], al[mt], bh[q][2], bh[q][3]);
                }
        }

        if (it + 3 < NIT) issue(it + 3);
        else CPA_COMMIT();   // empty group keeps wait count uniform
    }

    // ---- epilogue ----
    const int rowb = mtile * BM + rm + (lane >> 2);
    const int colb = ntile * BN + nb + (lane & 3) * 2;
#pragma unroll
    for (int mt = 0; mt < 2; ++mt) {
#pragma unroll
        for (int nt = 0; nt < 8; ++nt) {
            float* p = C + (size_t)(rowb + mt * 16) * N + colb + nt * 8;
            *(float2*)p                   = make_float2(acc[mt][nt][0], acc[mt][nt][1]);
            *(float2*)(p + 8 * (size_t)N) = make_float2(acc[mt][nt][2], acc[mt][nt][3]);
        }
    }
}

// ============================================================================
// Window attention v2: one block per (head, window), 128 threads.
// Load phase uses bulk cp.async gather (no serialized LDG chains), then
// RoPE is applied in-place in smem. Scores/AV in packed f32x2.
// ============================================================================
__global__ __launch_bounds__(128) void window_attn_kernel(
    const float* __restrict__ qkv,
    uint16_t* __restrict__ atthi, uint16_t* __restrict__ attlo)
{
    __shared__ __align__(16) float Qs[L * 68];
    __shared__ __align__(16) float Ks[L * 68];
    __shared__ __align__(16) float Vs[L * 64];
    __shared__ float S[L * 52];
    __shared__ float qn[L], kn[L];
    __shared__ int grows[L];

    const int h   = blockIdx.x;
    const int w   = blockIdx.y;
    const int tid = threadIdx.x;
    const int lane = tid & 31;
    const int warp = tid >> 5;
    const int b   = w >> 10;
    const int rem = w & 1023;
    const int wh  = rem >> 5, ww = rem & 31;

    if (tid < L) {
        int ty = tid / WS, tx = tid - ty * WS;
        int y = wh * WS + ty + SHIFT; if (y >= IMG) y -= IMG;
        int x = ww * WS + tx + SHIFT; if (x >= IMG) x -= IMG;
        grows[tid] = b * (IMG * IMG) + y * IMG + x;
    }
    __syncthreads();

    // ---- bulk gather: 147 rows x 16 chunks of 16B via cp.async ----
    {
        const uint32_t qs_b = smem_u32(Qs);
        const uint32_t ks_b = smem_u32(Ks);
        const uint32_t vs_b = smem_u32(Vs);
        for (int c = tid; c < 3 * L * 16; c += 128) {
            int rowk = c >> 4, ch = c & 15;
            int kind = rowk / L;            // 0=q,1=k,2=v
            int rw   = rowk - kind * L;
            const float* src = qkv + (size_t)grows[rw] * (3 * DIM)
                             + (size_t)kind * DIM + h * HD + ch * 4;
            uint32_t dst;
            if (kind == 0)      dst = qs_b + rw * 272 + ch * 16;
            else if (kind == 1) dst = ks_b + rw * 272 + ch * 16;
            else                dst = vs_b + rw * 256 + ch * 16;
            CPA16(dst, src);
        }
        CPA_COMMIT();
        CPA_WAITALL();
        __syncthreads();
    }

    // ---- RoPE in place (q and k tiles) ----
    for (int r = warp; r < 2 * L; r += 4) {
        float* T = (r < L) ? Qs : Ks;
        int rw = (r < L) ? r : r - L;
        float t1 = T[rw * 68 + lane];
        float t2 = T[rw * 68 + 32 + lane];
        float s = g_sin[rw * 32 + lane];
        float c = g_cos[rw * 32 + lane];
        T[rw * 68 + lane]      = t1 * c - t2 * s;
        T[rw * 68 + 32 + lane] = t1 * s + t2 * c;
    }
    __syncthreads();

    // ---- norms ----
    if (tid < L) {
        float ssq = 0.0f;
#pragma unroll
        for (int d4 = 0; d4 < 16; ++d4) {
            float4 v = *(const float4*)&Ks[tid * 68 + d4 * 4];
            ssq += v.x * v.x + v.y * v.y + v.z * v.z + v.w * v.w;
        }
        kn[tid] = 1.0f / fmaxf(sqrtf(ssq), 1e-12f);
    } else if (tid >= 64 && tid < 64 + L) {
        int i = tid - 64;
        float ssq = 0.0f;
#pragma unroll
        for (int d4 = 0; d4 < 16; ++d4) {
            float4 v = *(const float4*)&Qs[i * 68 + d4 * 4];
            ssq += v.x * v.x + v.y * v.y + v.z * v.z + v.w * v.w;
        }
        qn[i] = 100.0f / fmaxf(sqrtf(ssq), 1e-12f);
    }
    __syncthreads();

    // ---- scores: 98 threads, packed f32x2 dots ----
    if (tid < 2 * L) {
        int g = (tid >= L) ? 1 : 0;
        int i = tid - g * L;
        unsigned long long qp[32];
#pragma unroll
        for (int d4 = 0; d4 < 16; ++d4) {
            float4 v = *(const float4*)&Qs[i * 68 + d4 * 4];
            qp[d4 * 2]     = pk2(v.x, v.y);
            qp[d4 * 2 + 1] = pk2(v.z, v.w);
        }
        float qs = qn[i];
        int j0 = g ? 25 : 0, j1 = g ? L : 25;
        for (int j = j0; j < j1; ++j) {
            unsigned long long a0 = 0, a1 = 0, a2 = 0, a3 = 0;
#pragma unroll
            for (int d4 = 0; d4 < 8; ++d4) {
                float4 k0 = *(const float4*)&Ks[j * 68 + d4 * 8];
                float4 k1 = *(const float4*)&Ks[j * 68 + d4 * 8 + 4];
                fma2(a0, qp[d4 * 4],     pk2(k0.x, k0.y));
                fma2(a1, qp[d4 * 4 + 1], pk2(k0.z, k0.w));
                fma2(a2, qp[d4 * 4 + 2], pk2(k1.x, k1.y));
                fma2(a3, qp[d4 * 4 + 3], pk2(k1.z, k1.w));
            }
            float2 r0 = upk2(a0), r1 = upk2(a1), r2 = upk2(a2), r3 = upk2(a3);
            float dot = (r0.x + r0.y) + (r1.x + r1.y) + (r2.x + r2.y) + (r3.x + r3.y);
            S[i * 52 + j] = dot * (qs * kn[j]);
        }
    }
    __syncthreads();

    // ---- softmax per row ----
    if (tid < L) {
        float mx = -1e30f;
        for (int j = 0; j < L; ++j) mx = fmaxf(mx, S[tid * 52 + j]);
        float sum = 0.0f;
        for (int j = 0; j < L; ++j) {
            float e = __expf(S[tid * 52 + j] - mx);
            S[tid * 52 + j] = e;
            sum += e;
        }
        float inv = 1.0f / sum;
        for (int j = 0; j < L; ++j) S[tid * 52 + j] *= inv;
    }
    __syncthreads();

    // ---- AV: 98 threads, packed f32x2 ----
    if (tid < 2 * L) {
        int g = (tid >= L) ? 1 : 0;
        int i = tid - g * L;
        unsigned long long ov[16];
#pragma unroll
        for (int d = 0; d < 16; ++d) ov[d] = 0ull;
        for (int j = 0; j < L; ++j) {
            float wgt = S[i * 52 + j];
            unsigned long long wp = pk2(wgt, wgt);
#pragma unroll
            for (int d4 = 0; d4 < 4; ++d4) {
                float4 v0 = *(const float4*)&Vs[j * 64 + g * 32 + d4 * 8];
                float4 v1 = *(const float4*)&Vs[j * 64 + g * 32 + d4 * 8 + 4];
                fma2(ov[d4 * 4],     wp, pk2(v0.x, v0.y));
                fma2(ov[d4 * 4 + 1], wp, pk2(v0.z, v0.w));
                fma2(ov[d4 * 4 + 2], wp, pk2(v1.x, v1.y));
                fma2(ov[d4 * 4 + 3], wp, pk2(v1.z, v1.w));
            }
        }
#pragma unroll
        for (int d = 0; d < 16; ++d) {
            float2 r = upk2(ov[d]);
            Qs[i * 68 + g * 32 + d * 2]     = r.x;
            Qs[i * 68 + g * 32 + d * 2 + 1] = r.y;
        }
    }
    __syncthreads();

    // ---- scatter store as bf16 hi/lo ----
    for (int t = warp; t < L; t += 4) {
        size_t o = (size_t)grows[t] * DIM + h * HD;
        float v0 = Qs[t * 68 + lane];
        float v1 = Qs[t * 68 + lane + 32];
        uint16_t h0, l0, h1, l1;
        split1(v0, h0, l0);
        split1(v1, h1, l1);
        atthi[o + lane]      = h0;
        attlo[o + lane]      = l0;
        atthi[o + lane + 32] = h1;
        attlo[o + lane + 32] = l1;
    }
}

// ---------------------------------------------------------------------------
extern "C" void kernel_launch(void* const* d_in, const int* in_sizes, int n_in,
                              void* d_out, int out_size)
{
    const float* x     = (const float*)d_in[0];
    const float* qkv_w = (const float*)d_in[1];
    const float* projw = (const float*)d_in[2];
    float* out = (float*)d_out;

    float *qkv_ptr;
    uint16_t *xhi, *xlo, *qwhi, *qwlo, *pwhi, *pwlo, *atthi, *attlo;
    cudaGetSymbolAddress((void**)&qkv_ptr, g_qkv);
    cudaGetSymbolAddress((void**)&xhi,  g_xhi);
    cudaGetSymbolAddress((void**)&xlo,  g_xlo);
    cudaGetSymbolAddress((void**)&qwhi, g_qwhi);
    cudaGetSymbolAddress((void**)&qwlo, g_qwlo);
    cudaGetSymbolAddress((void**)&pwhi, g_pwhi);
    cudaGetSymbolAddress((void**)&pwlo, g_pwlo);
    cudaGetSymbolAddress((void**)&atthi, g_atthi);
    cudaGetSymbolAddress((void**)&attlo, g_attlo);

    cudaFuncSetAttribute(gemm_presplit_kernel,
                         cudaFuncAttributeMaxDynamicSharedMemorySize, SMEM_GEMM);

    // Launch order: attention is launch #4 (the profiled slot).
    split_kernel<<<1024, 256>>>(x, xhi, xlo, (size_t)TOKENS * DIM / 4, 1);      // 1 (+rope)
    split_kernel<<<64, 256>>>(qkv_w, qwhi, qwlo, (size_t)3 * DIM * DIM / 4, 0); // 2

    // qkv = x @ qkv_w^T : M=100352, N=2304, K=768                               // 3
    gemm_presplit_kernel<<<dim3(3 * DIM / BN, TOKENS / BM), 256, SMEM_GEMM>>>(
        xhi, xlo, qwhi, qwlo, qkv_ptr, TOKENS, 3 * DIM, DIM);

    // windowed attention (writes bf16 hi/lo att)                               // 4 <-- profiled
    window_attn_kernel<<<dim3(NH, NWIN), 128>>>(qkv_ptr, atthi, attlo);

    split_kernel<<<32, 256>>>(projw, pwhi, pwlo, (size_t)DIM * DIM / 4, 0);     // 5

    // out = att @ proj_w^T : M=100352, N=768, K=768                             // 6
    gemm_presplit_kernel<<<dim3(DIM / BN, TOKENS / BM), 256, SMEM_GEMM>>>(
        atthi, attlo, pwhi, pwlo, out, TOKENS, DIM, DIM);
}

// round 14
// speedup vs baseline: 1.3874x; 1.0396x over previous
#include <cuda_runtime.h>
#include <math.h>
#include <stdint.h>

// Problem constants (fixed by setup_inputs)
#define BATCH   2
#define IMG     224
#define TOKENS  (BATCH*IMG*IMG)   // 100352
#define DIM     768
#define NH      12
#define HD      64
#define WS      7
#define L       (WS*WS)           // 49
#define NWIN    (BATCH*(IMG/WS)*(IMG/WS))  // 2048
#define SHIFT   3

// Scratch (device globals: allocation is forbidden in kernel_launch)
__device__ float    g_qkv[(size_t)TOKENS * 3 * DIM];
__device__ uint16_t g_xhi[(size_t)TOKENS * DIM];
__device__ uint16_t g_xlo[(size_t)TOKENS * DIM];
__device__ uint16_t g_qwhi[(size_t)3 * DIM * DIM];
__device__ uint16_t g_qwlo[(size_t)3 * DIM * DIM];
__device__ uint16_t g_pwhi[(size_t)DIM * DIM];
__device__ uint16_t g_pwlo[(size_t)DIM * DIM];
__device__ uint16_t g_atthi[(size_t)TOKENS * DIM];
__device__ uint16_t g_attlo[(size_t)TOKENS * DIM];
__device__ float    g_sin[L * 32];
__device__ float    g_cos[L * 32];

// ============================================================================
// helpers
// ============================================================================
__device__ __forceinline__ uint32_t smem_u32(const void* p) {
    uint32_t a;
    asm("{ .reg .u64 t; cvta.to.shared.u64 t, %1; cvt.u32.u64 %0, t; }" : "=r"(a) : "l"(p));
    return a;
}

__device__ __forceinline__ void split_pack(float x, float y, uint32_t& hi, uint32_t& lo) {
    asm("cvt.rn.bf16x2.f32 %0, %1, %2;" : "=r"(hi) : "f"(y), "f"(x));
    float hx = __uint_as_float(hi << 16);
    float hy = __uint_as_float(hi & 0xffff0000u);
    float lx = x - hx;
    float ly = y - hy;
    asm("cvt.rn.bf16x2.f32 %0, %1, %2;" : "=r"(lo) : "f"(ly), "f"(lx));
}

__device__ __forceinline__ void split1(float x, uint16_t& h, uint16_t& l) {
    uint16_t hh;
    asm("cvt.rn.bf16.f32 %0, %1;" : "=h"(hh) : "f"(x));
    float hf = __uint_as_float(((uint32_t)hh) << 16);
    asm("cvt.rn.bf16.f32 %0, %1;" : "=h"(l) : "f"(x - hf));
    h = hh;
}

#define CPA16(dst, src) \
    asm volatile("cp.async.cg.shared.global [%0], [%1], 16;" :: "r"(dst), "l"(src) : "memory")
#define CPA_COMMIT()  asm volatile("cp.async.commit_group;" ::: "memory")
#define CPA_WAIT2()   asm volatile("cp.async.wait_group 2;" ::: "memory")
#define CPA_WAITALL() asm volatile("cp.async.wait_all;" ::: "memory")

#define LDSM4(r, addr) \
    asm volatile("ldmatrix.sync.aligned.m8n8.x4.shared.b16 {%0,%1,%2,%3}, [%4];" \
        : "=r"((r)[0]), "=r"((r)[1]), "=r"((r)[2]), "=r"((r)[3]) : "r"(addr))

#define LDSM4T(r, addr) \
    asm volatile("ldmatrix.sync.aligned.m8n8.x4.trans.shared.b16 {%0,%1,%2,%3}, [%4];" \
        : "=r"((r)[0]), "=r"((r)[1]), "=r"((r)[2]), "=r"((r)[3]) : "r"(addr))

#define MMA16816(d, a, b0, b1) \
    asm volatile("mma.sync.aligned.m16n8k16.row.col.f32.bf16.bf16.f32 " \
        "{%0,%1,%2,%3},{%4,%5,%6,%7},{%8,%9},{%0,%1,%2,%3};" \
        : "+f"((d)[0]), "+f"((d)[1]), "+f"((d)[2]), "+f"((d)[3]) \
        : "r"((a)[0]), "r"((a)[1]), "r"((a)[2]), "r"((a)[3]), "r"(b0), "r"(b1))

// ============================================================================
// fp32 -> bf16 hi/lo split pre-pass (optionally also builds RoPE tables)
// ============================================================================
__global__ void split_kernel(const float* __restrict__ src,
                             uint16_t* __restrict__ hi, uint16_t* __restrict__ lo,
                             size_t n4, int do_rope)
{
    if (do_rope && blockIdx.x == 0) {
        for (int i = threadIdx.x; i < L * 32; i += blockDim.x) {
            int tok = i >> 5, d = i & 31;
            int ty = tok / WS, tx = tok - ty * WS;
            int f = d & 15;
            float inv = powf(100.0f, -((float)f) / 16.0f);
            float ang = ((d < 16) ? (float)ty : (float)tx) * inv;
            g_sin[i] = sinf(ang);
            g_cos[i] = cosf(ang);
        }
    }
    size_t idx = (size_t)blockIdx.x * blockDim.x + threadIdx.x;
    size_t stride = (size_t)gridDim.x * blockDim.x;
    for (; idx < n4; idx += stride) {
        float4 v = ((const float4*)src)[idx];
        uint32_t h0, l0, h1, l1;
        split_pack(v.x, v.y, h0, l0);
        split_pack(v.z, v.w, h1, l1);
        ((uint2*)hi)[idx] = make_uint2(h0, h1);
        ((uint2*)lo)[idx] = make_uint2(l0, l1);
    }
}

// ============================================================================
// 3x-BF16-split GEMM (R8/R13 configuration — empirical best):
// CTA tile 128x128, BK=16, 256 threads (8 warps, 4m x 2n), 4-stage, 2 CTA/SM.
// ============================================================================
#define BM 128
#define BN 128
#define BK 16
#define PADB 48
#define A_LO  6144u
#define B_HI  12288u
#define B_LO  18432u
#define BUF_B 24576u
#define SMEM_GEMM (4u * BUF_B)   // 98304

__global__ __launch_bounds__(256, 2) void gemm_presplit_kernel(
    const uint16_t* __restrict__ Ahi, const uint16_t* __restrict__ Alo,
    const uint16_t* __restrict__ Bhi, const uint16_t* __restrict__ Blo,
    float* __restrict__ C, int M, int N, int K)
{
    extern __shared__ char smem[];
    const uint32_t sb = smem_u32(smem);
    const int tid  = threadIdx.x;
    const int lane = tid & 31;
    const int wid  = tid >> 5;
    const int mtile = blockIdx.y, ntile = blockIdx.x;
    const int rm = (wid & 3) * 32;
    const int nb = (wid >> 2) * 64;

    const int row = tid >> 1, half = tid & 1;
    const uint16_t* pAhi = Ahi + (size_t)(mtile * BM + row) * K + half * 8;
    const uint16_t* pAlo = Alo + (size_t)(mtile * BM + row) * K + half * 8;
    const uint16_t* pBhi = Bhi + (size_t)(ntile * BN + row) * K + half * 8;
    const uint16_t* pBlo = Blo + (size_t)(ntile * BN + row) * K + half * 8;

    const uint32_t dA = sb + (uint32_t)(row * PADB + half * 16);
    const uint32_t dB = sb + B_HI + (uint32_t)(row * PADB + half * 16);

    auto issue = [&](int s) {
        const uint32_t off = (uint32_t)(s & 3) * BUF_B;
        const int k0 = s * BK;
        CPA16(dA + off,                 pAhi + k0);
        CPA16(dA + off + A_LO,          pAlo + k0);
        CPA16(dB + off,                 pBhi + k0);
        CPA16(dB + off + (B_LO - B_HI), pBlo + k0);
        CPA_COMMIT();
    };

    float acc[2][8][4];
#pragma unroll
    for (int mt = 0; mt < 2; ++mt)
#pragma unroll
        for (int nt = 0; nt < 8; ++nt)
#pragma unroll
            for (int e = 0; e < 4; ++e) acc[mt][nt][e] = 0.0f;

    const uint32_t a_l = sb + (uint32_t)((rm + (lane & 15)) * PADB + (lane >> 4) * 16);
    const uint32_t b_l = sb + B_HI + (uint32_t)((nb + (lane & 7) + ((lane >> 4) << 3)) * PADB
                                                + ((lane >> 3) & 1) * 16);

    const int NIT = K / BK;
    issue(0); issue(1); issue(2);

    for (int it = 0; it < NIT; ++it) {
        CPA_WAIT2();
        __syncthreads();
        const uint32_t so = (uint32_t)(it & 3) * BUF_B;

        uint32_t ah[2][4], al[2][4];
#pragma unroll
        for (int mt = 0; mt < 2; ++mt) {
            LDSM4(ah[mt], a_l + so + mt * (16 * PADB));
            LDSM4(al[mt], a_l + so + A_LO + mt * (16 * PADB));
        }

#pragma unroll
        for (int hf = 0; hf < 2; ++hf) {
            uint32_t bh[2][4], bl[2][4];
#pragma unroll
            for (int q = 0; q < 2; ++q) {
                const int nt2 = hf * 2 + q;
                LDSM4(bh[q], b_l + so + nt2 * (16 * PADB));
                LDSM4(bl[q], b_l + so + (B_LO - B_HI) + nt2 * (16 * PADB));
            }
#pragma unroll
            for (int mt = 0; mt < 2; ++mt)
#pragma unroll
                for (int q = 0; q < 2; ++q) {
                    MMA16816(acc[mt][hf * 4 + 2 * q],     ah[mt], bh[q][0], bh[q][1]);
                    MMA16816(acc[mt][hf * 4 + 2 * q + 1], ah[mt], bh[q][2], bh[q][3]);
                }
#pragma unroll
            for (int mt = 0; mt < 2; ++mt)
#pragma unroll
                for (int q = 0; q < 2; ++q) {
                    MMA16816(acc[mt][hf * 4 + 2 * q],     ah[mt], bl[q][0], bl[q][1]);
                    MMA16816(acc[mt][hf * 4 + 2 * q + 1], ah[mt], bl[q][2], bl[q][3]);
                }
#pragma unroll
            for (int mt = 0; mt < 2; ++mt)
#pragma unroll
                for (int q = 0; q < 2; ++q) {
                    MMA16816(acc[mt][hf * 4 + 2 * q],     al[mt], bh[q][0], bh[q][1]);
                    MMA16816(acc[mt][hf * 4 + 2 * q + 1], al[mt], bh[q][2], bh[q][3]);
                }
        }

        if (it + 3 < NIT) issue(it + 3);
        else CPA_COMMIT();
    }

    const int rowb = mtile * BM + rm + (lane >> 2);
    const int colb = ntile * BN + nb + (lane & 3) * 2;
#pragma unroll
    for (int mt = 0; mt < 2; ++mt) {
#pragma unroll
        for (int nt = 0; nt < 8; ++nt) {
            float* p = C + (size_t)(rowb + mt * 16) * N + colb + nt * 8;
            *(float2*)p                   = make_float2(acc[mt][nt][0], acc[mt][nt][1]);
            *(float2*)(p + 8 * (size_t)N) = make_float2(acc[mt][nt][2], acc[mt][nt][3]);
        }
    }
}

// ============================================================================
// Window attention v3 (tensor-core): one block per (head, window), 128 thr.
// cp.async gather -> RoPE -> norms -> scaled bf16 hi/lo tiles (64x64, padded)
// -> S=QK^T via mma (logits directly) -> register softmax (shfl) -> P split
// in regs -> O=PV via mma with ldmatrix.trans B -> staged coalesced store.
// ============================================================================
// smem byte offsets
#define AO_GROWS 0
#define AO_QN    256
#define AO_KN    512
#define AO_QS    768u                 // fp32 49x68
#define AO_KS    (AO_QS + 13328u)
#define AO_VS    (AO_KS + 13328u)     // fp32 49x64
#define AO_QH    (AO_VS + 12544u)     // bf16 tiles 64 rows x 144B
#define AO_QL    (AO_QH + 9216u)
#define AO_KH    (AO_QL + 9216u)
#define AO_KL    (AO_KH + 9216u)
#define AO_VH    (AO_KL + 9216u)
#define AO_VL    (AO_VH + 9216u)
#define SMEM_ATTN (AO_VL + 9216u)     // 95264

__global__ __launch_bounds__(128) void window_attn_kernel(
    const float* __restrict__ qkv,
    uint16_t* __restrict__ atthi, uint16_t* __restrict__ attlo)
{
    extern __shared__ char asm_[];
    const uint32_t sbase = smem_u32(asm_);
    int*   grows = (int*)(asm_ + AO_GROWS);
    float* qn    = (float*)(asm_ + AO_QN);
    float* kn    = (float*)(asm_ + AO_KN);
    float* Qs    = (float*)(asm_ + AO_QS);
    float* Ks    = (float*)(asm_ + AO_KS);
    float* Vs    = (float*)(asm_ + AO_VS);

    const int h   = blockIdx.x;
    const int w   = blockIdx.y;
    const int tid = threadIdx.x;
    const int lane = tid & 31;
    const int warp = tid >> 5;
    const int b   = w >> 10;
    const int rem = w & 1023;
    const int wh  = rem >> 5, ww = rem & 31;

    if (tid < L) {
        int ty = tid / WS, tx = tid - ty * WS;
        int y = wh * WS + ty + SHIFT; if (y >= IMG) y -= IMG;
        int x = ww * WS + tx + SHIFT; if (x >= IMG) x -= IMG;
        grows[tid] = b * (IMG * IMG) + y * IMG + x;
    }
    // zero all bf16 tiles (rows >= 49 must be zero for MMA padding)
    {
        float4 z = make_float4(0.f, 0.f, 0.f, 0.f);
        char* tb = asm_ + AO_QH;
        for (int i = tid; i < (int)(6 * 9216 / 16); i += 128)
            *(float4*)(tb + i * 16) = z;
    }
    __syncthreads();

    // ---- bulk gather: 147 rows x 16 chunks of 16B via cp.async ----
    for (int c = tid; c < 3 * L * 16; c += 128) {
        int rowk = c >> 4, ch = c & 15;
        int kind = rowk / L;
        int rw   = rowk - kind * L;
        const float* src = qkv + (size_t)grows[rw] * (3 * DIM)
                         + (size_t)kind * DIM + h * HD + ch * 4;
        uint32_t dst;
        if (kind == 0)      dst = sbase + AO_QS + rw * 272 + ch * 16;
        else if (kind == 1) dst = sbase + AO_KS + rw * 272 + ch * 16;
        else                dst = sbase + AO_VS + rw * 256 + ch * 16;
        CPA16(dst, src);
    }
    CPA_COMMIT();
    CPA_WAITALL();
    __syncthreads();

    // ---- RoPE in place (q and k) ----
    for (int r = warp; r < 2 * L; r += 4) {
        float* T = (r < L) ? Qs : Ks;
        int rw = (r < L) ? r : r - L;
        float t1 = T[rw * 68 + lane];
        float t2 = T[rw * 68 + 32 + lane];
        float s = g_sin[rw * 32 + lane];
        float c = g_cos[rw * 32 + lane];
        T[rw * 68 + lane]      = t1 * c - t2 * s;
        T[rw * 68 + 32 + lane] = t1 * s + t2 * c;
    }
    __syncthreads();

    // ---- norms: qn = 1/|q|, kn = 100/|k| ----
    if (tid < L) {
        float ssq = 0.0f;
#pragma unroll
        for (int d4 = 0; d4 < 16; ++d4) {
            float4 v = *(const float4*)&Ks[tid * 68 + d4 * 4];
            ssq += v.x * v.x + v.y * v.y + v.z * v.z + v.w * v.w;
        }
        kn[tid] = 100.0f / fmaxf(sqrtf(ssq), 1e-12f);
    } else if (tid >= 64 && tid < 64 + L) {
        int i = tid - 64;
        float ssq = 0.0f;
#pragma unroll
        for (int d4 = 0; d4 < 16; ++d4) {
            float4 v = *(const float4*)&Qs[i * 68 + d4 * 4];
            ssq += v.x * v.x + v.y * v.y + v.z * v.z + v.w * v.w;
        }
        qn[i] = 1.0f / fmaxf(sqrtf(ssq), 1e-12f);
    }
    __syncthreads();

    // ---- convert to scaled bf16 hi/lo tiles (row stride 144B) ----
    for (int it = tid; it < 3 * L * 16; it += 128) {
        int kind = it / (L * 16);
        int rm2  = it - kind * (L * 16);
        int rw = rm2 >> 4, ch = rm2 & 15;
        float4 v;
        float s;
        uint32_t dhi, dlo;
        if (kind == 0) {
            v = *(const float4*)&Qs[rw * 68 + ch * 4]; s = qn[rw];
            dhi = AO_QH; dlo = AO_QL;
        } else if (kind == 1) {
            v = *(const float4*)&Ks[rw * 68 + ch * 4]; s = kn[rw];
            dhi = AO_KH; dlo = AO_KL;
        } else {
            v = *(const float4*)&Vs[rw * 64 + ch * 4]; s = 1.0f;
            dhi = AO_VH; dlo = AO_VL;
        }
        uint32_t h0, l0, h1, l1;
        split_pack(v.x * s, v.y * s, h0, l0);
        split_pack(v.z * s, v.w * s, h1, l1);
        *(uint2*)(asm_ + dhi + rw * 144 + ch * 8) = make_uint2(h0, h1);
        *(uint2*)(asm_ + dlo + rw * 144 + ch * 8) = make_uint2(l0, l1);
    }
    __syncthreads();

    // ---- scores: S(64x64) = Qhat @ Khat^T, warp w -> m16 tile w ----
    float sacc[8][4];
#pragma unroll
    for (int nt = 0; nt < 8; ++nt)
#pragma unroll
        for (int e = 0; e < 4; ++e) sacc[nt][e] = 0.0f;

    {
        const uint32_t aq = sbase + AO_QH
            + (uint32_t)((warp * 16 + (lane & 15)) * 144 + (lane >> 4) * 16);
        const uint32_t bk = sbase + AO_KH
            + (uint32_t)(((lane & 7) + ((lane >> 4) << 3)) * 144 + ((lane >> 3) & 1) * 16);
        const uint32_t QLD = AO_QL - AO_QH;   // hi->lo tile delta (same for K)
#pragma unroll
        for (int ks = 0; ks < 4; ++ks) {
            uint32_t ah[4], al[4];
            LDSM4(ah, aq + ks * 32);
            LDSM4(al, aq + QLD + ks * 32);
#pragma unroll
            for (int nt2 = 0; nt2 < 4; ++nt2) {
                uint32_t bh[4], bl[4];
                LDSM4(bh, bk + nt2 * (16 * 144) + ks * 32);
                LDSM4(bl, bk + QLD + nt2 * (16 * 144) + ks * 32);
                MMA16816(sacc[2 * nt2],     ah, bh[0], bh[1]);
                MMA16816(sacc[2 * nt2 + 1], ah, bh[2], bh[3]);
                MMA16816(sacc[2 * nt2],     ah, bl[0], bl[1]);
                MMA16816(sacc[2 * nt2 + 1], ah, bl[2], bl[3]);
                MMA16816(sacc[2 * nt2],     al, bh[0], bh[1]);
                MMA16816(sacc[2 * nt2 + 1], al, bh[2], bh[3]);
            }
        }
    }

    // ---- register softmax (rows r=lane>>2 and r+8; cols masked j>=49) ----
    {
        float m0 = -1e30f, m1 = -1e30f;
#pragma unroll
        for (int nt = 0; nt < 8; ++nt) {
            int jb = nt * 8 + (lane & 3) * 2;
            if (jb >= L)     { sacc[nt][0] = -1e30f; sacc[nt][2] = -1e30f; }
            if (jb + 1 >= L) { sacc[nt][1] = -1e30f; sacc[nt][3] = -1e30f; }
            m0 = fmaxf(m0, fmaxf(sacc[nt][0], sacc[nt][1]));
            m1 = fmaxf(m1, fmaxf(sacc[nt][2], sacc[nt][3]));
        }
        m0 = fmaxf(m0, __shfl_xor_sync(0xffffffffu, m0, 1));
        m0 = fmaxf(m0, __shfl_xor_sync(0xffffffffu, m0, 2));
        m1 = fmaxf(m1, __shfl_xor_sync(0xffffffffu, m1, 1));
        m1 = fmaxf(m1, __shfl_xor_sync(0xffffffffu, m1, 2));
        float s0 = 0.0f, s1 = 0.0f;
#pragma unroll
        for (int nt = 0; nt < 8; ++nt) {
            sacc[nt][0] = __expf(sacc[nt][0] - m0); s0 += sacc[nt][0];
            sacc[nt][1] = __expf(sacc[nt][1] - m0); s0 += sacc[nt][1];
            sacc[nt][2] = __expf(sacc[nt][2] - m1); s1 += sacc[nt][2];
            sacc[nt][3] = __expf(sacc[nt][3] - m1); s1 += sacc[nt][3];
        }
        s0 += __shfl_xor_sync(0xffffffffu, s0, 1);
        s0 += __shfl_xor_sync(0xffffffffu, s0, 2);
        s1 += __shfl_xor_sync(0xffffffffu, s1, 1);
        s1 += __shfl_xor_sync(0xffffffffu, s1, 2);
        float i0 = 1.0f / s0, i1 = 1.0f / s1;
#pragma unroll
        for (int nt = 0; nt < 8; ++nt) {
            sacc[nt][0] *= i0; sacc[nt][1] *= i0;
            sacc[nt][2] *= i1; sacc[nt][3] *= i1;
        }
    }

    // ---- O(64x64) = P @ V via mma (P from regs, V via ldmatrix.trans) ----
    float oacc[8][4];
#pragma unroll
    for (int nt = 0; nt < 8; ++nt)
#pragma unroll
        for (int e = 0; e < 4; ++e) oacc[nt][e] = 0.0f;

    {
        const uint32_t bv = sbase + AO_VH
            + (uint32_t)(((lane & 7) + ((lane >> 3) & 1) * 8) * 144 + (lane >> 4) * 16);
        const uint32_t VLD = AO_VL - AO_VH;
#pragma unroll
        for (int jj = 0; jj < 4; ++jj) {
            uint32_t ph[4], pl[4];
            split_pack(sacc[2 * jj][0],     sacc[2 * jj][1],     ph[0], pl[0]);
            split_pack(sacc[2 * jj][2],     sacc[2 * jj][3],     ph[1], pl[1]);
            split_pack(sacc[2 * jj + 1][0], sacc[2 * jj + 1][1], ph[2], pl[2]);
            split_pack(sacc[2 * jj + 1][2], sacc[2 * jj + 1][3], ph[3], pl[3]);
#pragma unroll
            for (int nd2 = 0; nd2 < 4; ++nd2) {
                uint32_t vh[4], vl[4];
                LDSM4T(vh, bv + jj * (16 * 144) + nd2 * 32);
                LDSM4T(vl, bv + VLD + jj * (16 * 144) + nd2 * 32);
                MMA16816(oacc[2 * nd2],     ph, vh[0], vh[1]);
                MMA16816(oacc[2 * nd2 + 1], ph, vh[2], vh[3]);
                MMA16816(oacc[2 * nd2],     ph, vl[0], vl[1]);
                MMA16816(oacc[2 * nd2 + 1], ph, vl[2], vl[3]);
                MMA16816(oacc[2 * nd2],     pl, vh[0], vh[1]);
                MMA16816(oacc[2 * nd2 + 1], pl, vh[2], vh[3]);
            }
        }
    }

    // ---- stage O to fp32 smem (Qs reused), then coalesced bf16 store ----
    __syncthreads();   // all reads of Qs (convert phase) long done; reuse
    {
        int r0 = warp * 16 + (lane >> 2);
#pragma unroll
        for (int nt = 0; nt < 8; ++nt) {
            int d0 = nt * 8 + (lane & 3) * 2;
            if (r0 < L) {
                Qs[r0 * 68 + d0]     = oacc[nt][0];
                Qs[r0 * 68 + d0 + 1] = oacc[nt][1];
            }
            if (r0 + 8 < L) {
                Qs[(r0 + 8) * 68 + d0]     = oacc[nt][2];
                Qs[(r0 + 8) * 68 + d0 + 1] = oacc[nt][3];
            }
        }
    }
    __syncthreads();

    for (int t = warp; t < L; t += 4) {
        size_t o = (size_t)grows[t] * DIM + h * HD;
        float v0 = Qs[t * 68 + lane];
        float v1 = Qs[t * 68 + lane + 32];
        uint16_t h0, l0, h1, l1;
        split1(v0, h0, l0);
        split1(v1, h1, l1);
        atthi[o + lane]      = h0;
        attlo[o + lane]      = l0;
        atthi[o + lane + 32] = h1;
        attlo[o + lane + 32] = l1;
    }
}

// ---------------------------------------------------------------------------
extern "C" void kernel_launch(void* const* d_in, const int* in_sizes, int n_in,
                              void* d_out, int out_size)
{
    const float* x     = (const float*)d_in[0];
    const float* qkv_w = (const float*)d_in[1];
    const float* projw = (const float*)d_in[2];
    float* out = (float*)d_out;

    float *qkv_ptr;
    uint16_t *xhi, *xlo, *qwhi, *qwlo, *pwhi, *pwlo, *atthi, *attlo;
    cudaGetSymbolAddress((void**)&qkv_ptr, g_qkv);
    cudaGetSymbolAddress((void**)&xhi,  g_xhi);
    cudaGetSymbolAddress((void**)&xlo,  g_xlo);
    cudaGetSymbolAddress((void**)&qwhi, g_qwhi);
    cudaGetSymbolAddress((void**)&qwlo, g_qwlo);
    cudaGetSymbolAddress((void**)&pwhi, g_pwhi);
    cudaGetSymbolAddress((void**)&pwlo, g_pwlo);
    cudaGetSymbolAddress((void**)&atthi, g_atthi);
    cudaGetSymbolAddress((void**)&attlo, g_attlo);

    cudaFuncSetAttribute(gemm_presplit_kernel,
                         cudaFuncAttributeMaxDynamicSharedMemorySize, SMEM_GEMM);
    cudaFuncSetAttribute(window_attn_kernel,
                         cudaFuncAttributeMaxDynamicSharedMemorySize, SMEM_ATTN);

    // Launch order: attention is launch #4 (the profiled slot).
    split_kernel<<<1024, 256>>>(x, xhi, xlo, (size_t)TOKENS * DIM / 4, 1);      // 1 (+rope)
    split_kernel<<<64, 256>>>(qkv_w, qwhi, qwlo, (size_t)3 * DIM * DIM / 4, 0); // 2

    // qkv = x @ qkv_w^T                                                        // 3
    gemm_presplit_kernel<<<dim3(3 * DIM / BN, TOKENS / BM), 256, SMEM_GEMM>>>(
        xhi, xlo, qwhi, qwlo, qkv_ptr, TOKENS, 3 * DIM, DIM);

    // windowed attention (tensor-core)                                        // 4 <-- profiled
    window_attn_kernel<<<dim3(NH, NWIN), 128, SMEM_ATTN>>>(qkv_ptr, atthi, attlo);

    split_kernel<<<32, 256>>>(projw, pwhi, pwlo, (size_t)DIM * DIM / 4, 0);     // 5

    // out = att @ proj_w^T                                                     // 6
    gemm_presplit_kernel<<<dim3(DIM / BN, TOKENS / BM), 256, SMEM_GEMM>>>(
        atthi, attlo, pwhi, pwlo, out, TOKENS, DIM, DIM);
}

// round 15
// speedup vs baseline: 1.4984x; 1.0800x over previous
#include <cuda_runtime.h>
#include <math.h>
#include <stdint.h>

// Problem constants (fixed by setup_inputs)
#define BATCH   2
#define IMG     224
#define TOKENS  (BATCH*IMG*IMG)   // 100352
#define DIM     768
#define NH      12
#define HD      64
#define WS      7
#define L       (WS*WS)           // 49
#define NWIN    (BATCH*(IMG/WS)*(IMG/WS))  // 2048
#define SHIFT   3

// Scratch (device globals: allocation is forbidden in kernel_launch)
__device__ float    g_qkv[(size_t)TOKENS * 3 * DIM];
__device__ uint16_t g_xhi[(size_t)TOKENS * DIM];
__device__ uint16_t g_xlo[(size_t)TOKENS * DIM];
__device__ uint16_t g_qwhi[(size_t)3 * DIM * DIM];
__device__ uint16_t g_qwlo[(size_t)3 * DIM * DIM];
__device__ uint16_t g_pwhi[(size_t)DIM * DIM];
__device__ uint16_t g_pwlo[(size_t)DIM * DIM];
__device__ uint16_t g_atthi[(size_t)TOKENS * DIM];
__device__ uint16_t g_attlo[(size_t)TOKENS * DIM];
__device__ float    g_sin[L * 32];
__device__ float    g_cos[L * 32];

// ============================================================================
// helpers
// ============================================================================
__device__ __forceinline__ uint32_t smem_u32(const void* p) {
    uint32_t a;
    asm("{ .reg .u64 t; cvta.to.shared.u64 t, %1; cvt.u32.u64 %0, t; }" : "=r"(a) : "l"(p));
    return a;
}

__device__ __forceinline__ void split_pack(float x, float y, uint32_t& hi, uint32_t& lo) {
    asm("cvt.rn.bf16x2.f32 %0, %1, %2;" : "=r"(hi) : "f"(y), "f"(x));
    float hx = __uint_as_float(hi << 16);
    float hy = __uint_as_float(hi & 0xffff0000u);
    float lx = x - hx;
    float ly = y - hy;
    asm("cvt.rn.bf16x2.f32 %0, %1, %2;" : "=r"(lo) : "f"(ly), "f"(lx));
}

__device__ __forceinline__ void split1(float x, uint16_t& h, uint16_t& l) {
    uint16_t hh;
    asm("cvt.rn.bf16.f32 %0, %1;" : "=h"(hh) : "f"(x));
    float hf = __uint_as_float(((uint32_t)hh) << 16);
    asm("cvt.rn.bf16.f32 %0, %1;" : "=h"(l) : "f"(x - hf));
    h = hh;
}

#define CPA16(dst, src) \
    asm volatile("cp.async.cg.shared.global [%0], [%1], 16;" :: "r"(dst), "l"(src) : "memory")
#define CPA_COMMIT()  asm volatile("cp.async.commit_group;" ::: "memory")
#define CPA_WAIT2()   asm volatile("cp.async.wait_group 2;" ::: "memory")
#define CPA_WAITALL() asm volatile("cp.async.wait_all;" ::: "memory")

#define LDSM4(r, addr) \
    asm volatile("ldmatrix.sync.aligned.m8n8.x4.shared.b16 {%0,%1,%2,%3}, [%4];" \
        : "=r"((r)[0]), "=r"((r)[1]), "=r"((r)[2]), "=r"((r)[3]) : "r"(addr))

#define LDSM4T(r, addr) \
    asm volatile("ldmatrix.sync.aligned.m8n8.x4.trans.shared.b16 {%0,%1,%2,%3}, [%4];" \
        : "=r"((r)[0]), "=r"((r)[1]), "=r"((r)[2]), "=r"((r)[3]) : "r"(addr))

#define MMA16816(d, a, b0, b1) \
    asm volatile("mma.sync.aligned.m16n8k16.row.col.f32.bf16.bf16.f32 " \
        "{%0,%1,%2,%3},{%4,%5,%6,%7},{%8,%9},{%0,%1,%2,%3};" \
        : "+f"((d)[0]), "+f"((d)[1]), "+f"((d)[2]), "+f"((d)[3]) \
        : "r"((a)[0]), "r"((a)[1]), "r"((a)[2]), "r"((a)[3]), "r"(b0), "r"(b1))

// ============================================================================
// fp32 -> bf16 hi/lo split pre-pass (optionally also builds RoPE tables)
// ============================================================================
__global__ void split_kernel(const float* __restrict__ src,
                             uint16_t* __restrict__ hi, uint16_t* __restrict__ lo,
                             size_t n4, int do_rope)
{
    if (do_rope && blockIdx.x == 0) {
        for (int i = threadIdx.x; i < L * 32; i += blockDim.x) {
            int tok = i >> 5, d = i & 31;
            int ty = tok / WS, tx = tok - ty * WS;
            int f = d & 15;
            float inv = powf(100.0f, -((float)f) / 16.0f);
            float ang = ((d < 16) ? (float)ty : (float)tx) * inv;
            g_sin[i] = sinf(ang);
            g_cos[i] = cosf(ang);
        }
    }
    size_t idx = (size_t)blockIdx.x * blockDim.x + threadIdx.x;
    size_t stride = (size_t)gridDim.x * blockDim.x;
    for (; idx < n4; idx += stride) {
        float4 v = ((const float4*)src)[idx];
        uint32_t h0, l0, h1, l1;
        split_pack(v.x, v.y, h0, l0);
        split_pack(v.z, v.w, h1, l1);
        ((uint2*)hi)[idx] = make_uint2(h0, h1);
        ((uint2*)lo)[idx] = make_uint2(l0, l1);
    }
}

// ============================================================================
// 3x-BF16-split GEMM (R8/R13 configuration — empirical best):
// CTA tile 128x128, BK=16, 256 threads (8 warps, 4m x 2n), 4-stage, 2 CTA/SM.
// ============================================================================
#define BM 128
#define BN 128
#define BK 16
#define PADB 48
#define A_LO  6144u
#define B_HI  12288u
#define B_LO  18432u
#define BUF_B 24576u
#define SMEM_GEMM (4u * BUF_B)   // 98304

__global__ __launch_bounds__(256, 2) void gemm_presplit_kernel(
    const uint16_t* __restrict__ Ahi, const uint16_t* __restrict__ Alo,
    const uint16_t* __restrict__ Bhi, const uint16_t* __restrict__ Blo,
    float* __restrict__ C, int M, int N, int K)
{
    extern __shared__ char smem[];
    const uint32_t sb = smem_u32(smem);
    const int tid  = threadIdx.x;
    const int lane = tid & 31;
    const int wid  = tid >> 5;
    const int mtile = blockIdx.y, ntile = blockIdx.x;
    const int rm = (wid & 3) * 32;
    const int nb = (wid >> 2) * 64;

    const int row = tid >> 1, half = tid & 1;
    const uint16_t* pAhi = Ahi + (size_t)(mtile * BM + row) * K + half * 8;
    const uint16_t* pAlo = Alo + (size_t)(mtile * BM + row) * K + half * 8;
    const uint16_t* pBhi = Bhi + (size_t)(ntile * BN + row) * K + half * 8;
    const uint16_t* pBlo = Blo + (size_t)(ntile * BN + row) * K + half * 8;

    const uint32_t dA = sb + (uint32_t)(row * PADB + half * 16);
    const uint32_t dB = sb + B_HI + (uint32_t)(row * PADB + half * 16);

    auto issue = [&](int s) {
        const uint32_t off = (uint32_t)(s & 3) * BUF_B;
        const int k0 = s * BK;
        CPA16(dA + off,                 pAhi + k0);
        CPA16(dA + off + A_LO,          pAlo + k0);
        CPA16(dB + off,                 pBhi + k0);
        CPA16(dB + off + (B_LO - B_HI), pBlo + k0);
        CPA_COMMIT();
    };

    float acc[2][8][4];
#pragma unroll
    for (int mt = 0; mt < 2; ++mt)
#pragma unroll
        for (int nt = 0; nt < 8; ++nt)
#pragma unroll
            for (int e = 0; e < 4; ++e) acc[mt][nt][e] = 0.0f;

    const uint32_t a_l = sb + (uint32_t)((rm + (lane & 15)) * PADB + (lane >> 4) * 16);
    const uint32_t b_l = sb + B_HI + (uint32_t)((nb + (lane & 7) + ((lane >> 4) << 3)) * PADB
                                                + ((lane >> 3) & 1) * 16);

    const int NIT = K / BK;
    issue(0); issue(1); issue(2);

    for (int it = 0; it < NIT; ++it) {
        CPA_WAIT2();
        __syncthreads();
        const uint32_t so = (uint32_t)(it & 3) * BUF_B;

        uint32_t ah[2][4], al[2][4];
#pragma unroll
        for (int mt = 0; mt < 2; ++mt) {
            LDSM4(ah[mt], a_l + so + mt * (16 * PADB));
            LDSM4(al[mt], a_l + so + A_LO + mt * (16 * PADB));
        }

#pragma unroll
        for (int hf = 0; hf < 2; ++hf) {
            uint32_t bh[2][4], bl[2][4];
#pragma unroll
            for (int q = 0; q < 2; ++q) {
                const int nt2 = hf * 2 + q;
                LDSM4(bh[q], b_l + so + nt2 * (16 * PADB));
                LDSM4(bl[q], b_l + so + (B_LO - B_HI) + nt2 * (16 * PADB));
            }
#pragma unroll
            for (int mt = 0; mt < 2; ++mt)
#pragma unroll
                for (int q = 0; q < 2; ++q) {
                    MMA16816(acc[mt][hf * 4 + 2 * q],     ah[mt], bh[q][0], bh[q][1]);
                    MMA16816(acc[mt][hf * 4 + 2 * q + 1], ah[mt], bh[q][2], bh[q][3]);
                }
#pragma unroll
            for (int mt = 0; mt < 2; ++mt)
#pragma unroll
                for (int q = 0; q < 2; ++q) {
                    MMA16816(acc[mt][hf * 4 + 2 * q],     ah[mt], bl[q][0], bl[q][1]);
                    MMA16816(acc[mt][hf * 4 + 2 * q + 1], ah[mt], bl[q][2], bl[q][3]);
                }
#pragma unroll
            for (int mt = 0; mt < 2; ++mt)
#pragma unroll
                for (int q = 0; q < 2; ++q) {
                    MMA16816(acc[mt][hf * 4 + 2 * q],     al[mt], bh[q][0], bh[q][1]);
                    MMA16816(acc[mt][hf * 4 + 2 * q + 1], al[mt], bh[q][2], bh[q][3]);
                }
        }

        if (it + 3 < NIT) issue(it + 3);
        else CPA_COMMIT();
    }

    const int rowb = mtile * BM + rm + (lane >> 2);
    const int colb = ntile * BN + nb + (lane & 3) * 2;
#pragma unroll
    for (int mt = 0; mt < 2; ++mt) {
#pragma unroll
        for (int nt = 0; nt < 8; ++nt) {
            float* p = C + (size_t)(rowb + mt * 16) * N + colb + nt * 8;
            *(float2*)p                   = make_float2(acc[mt][nt][0], acc[mt][nt][1]);
            *(float2*)(p + 8 * (size_t)N) = make_float2(acc[mt][nt][2], acc[mt][nt][3]);
        }
    }
}

// ============================================================================
// Window attention v4 (tensor-core, compact smem): 128 threads, 4 CTAs/SM.
// fp32 staging is ALIASED inside the bf16 tile regions; conversion is done
// in place via register staging + barrier. Only V pad rows need zeroing.
// ============================================================================
#define AO_GROWS 0
#define AO_QN    256
#define AO_KN    512
#define AO_QH    768u
#define AO_QL    (AO_QH + 9216u)    // 9984
#define AO_KH    (AO_QL + 9216u)    // 19200
#define AO_KL    (AO_KH + 9216u)    // 28416
#define AO_VH    (AO_KL + 9216u)    // 37632
#define AO_VL    (AO_VH + 9216u)    // 46848
#define SMEM_ATTN (AO_VL + 9216u)   // 56064

__global__ __launch_bounds__(128, 4) void window_attn_kernel(
    const float* __restrict__ qkv,
    uint16_t* __restrict__ atthi, uint16_t* __restrict__ attlo)
{
    extern __shared__ char asm_[];
    const uint32_t sbase = smem_u32(asm_);
    int*   grows = (int*)(asm_ + AO_GROWS);
    float* qn    = (float*)(asm_ + AO_QN);
    float* kn    = (float*)(asm_ + AO_KN);
    float* Qf    = (float*)(asm_ + AO_QH);   // fp32 staging aliases (stride 68)
    float* Kf    = (float*)(asm_ + AO_KH);
    float* Vf    = (float*)(asm_ + AO_VH);   // stride 64

    const int h   = blockIdx.x;
    const int w   = blockIdx.y;
    const int tid = threadIdx.x;
    const int lane = tid & 31;
    const int warp = tid >> 5;
    const int b   = w >> 10;
    const int rem = w & 1023;
    const int wh  = rem >> 5, ww = rem & 31;

    if (tid < L) {
        int ty = tid / WS, tx = tid - ty * WS;
        int y = wh * WS + ty + SHIFT; if (y >= IMG) y -= IMG;
        int x = ww * WS + tx + SHIFT; if (x >= IMG) x -= IMG;
        grows[tid] = b * (IMG * IMG) + y * IMG + x;
    }
    __syncthreads();

    // ---- bulk gather: fp32 rows into tile-region aliases (flat loops) ----
    for (int c = tid; c < L * 16; c += 128) {
        int rw = c >> 4, ch = c & 15;
        const float* base = qkv + (size_t)grows[rw] * (3 * DIM) + h * HD + ch * 4;
        CPA16(sbase + AO_QH + rw * 272 + ch * 16, base);
        CPA16(sbase + AO_KH + rw * 272 + ch * 16, base + DIM);
        CPA16(sbase + AO_VH + rw * 256 + ch * 16, base + 2 * DIM);
    }
    CPA_COMMIT();
    CPA_WAITALL();
    __syncthreads();

    // ---- RoPE in place (q and k, fp32) ----
    for (int r = warp; r < 2 * L; r += 4) {
        float* T = (r < L) ? Qf : Kf;
        int rw = (r < L) ? r : r - L;
        float t1 = T[rw * 68 + lane];
        float t2 = T[rw * 68 + 32 + lane];
        float s = g_sin[rw * 32 + lane];
        float c = g_cos[rw * 32 + lane];
        T[rw * 68 + lane]      = t1 * c - t2 * s;
        T[rw * 68 + 32 + lane] = t1 * s + t2 * c;
    }
    __syncthreads();

    // ---- norms: qn = 1/|q|, kn = 100/|k| ----
    if (tid < L) {
        float ssq = 0.0f;
#pragma unroll
        for (int d4 = 0; d4 < 16; ++d4) {
            float4 v = *(const float4*)&Kf[tid * 68 + d4 * 4];
            ssq += v.x * v.x + v.y * v.y + v.z * v.z + v.w * v.w;
        }
        kn[tid] = 100.0f / fmaxf(sqrtf(ssq), 1e-12f);
    } else if (tid >= 64 && tid < 64 + L) {
        int i = tid - 64;
        float ssq = 0.0f;
#pragma unroll
        for (int d4 = 0; d4 < 16; ++d4) {
            float4 v = *(const float4*)&Qf[i * 68 + d4 * 4];
            ssq += v.x * v.x + v.y * v.y + v.z * v.z + v.w * v.w;
        }
        qn[i] = 1.0f / fmaxf(sqrtf(ssq), 1e-12f);
    }
    __syncthreads();

    // ---- in-place conversion to scaled bf16 hi/lo (register staging) ----
    {
        float4 r[7];
        // Q
#pragma unroll
        for (int i = 0; i < 7; ++i) {
            int c = tid + i * 128;
            if (c < L * 16) r[i] = *(const float4*)(asm_ + AO_QH + (c >> 4) * 272 + (c & 15) * 16);
        }
        __syncthreads();
#pragma unroll
        for (int i = 0; i < 7; ++i) {
            int c = tid + i * 128;
            if (c < L * 16) {
                int rw = c >> 4, ch = c & 15;
                float s = qn[rw];
                uint32_t h0, l0, h1, l1;
                split_pack(r[i].x * s, r[i].y * s, h0, l0);
                split_pack(r[i].z * s, r[i].w * s, h1, l1);
                *(uint2*)(asm_ + AO_QH + rw * 144 + ch * 8) = make_uint2(h0, h1);
                *(uint2*)(asm_ + AO_QL + rw * 144 + ch * 8) = make_uint2(l0, l1);
            }
        }
        // K
#pragma unroll
        for (int i = 0; i < 7; ++i) {
            int c = tid + i * 128;
            if (c < L * 16) r[i] = *(const float4*)(asm_ + AO_KH + (c >> 4) * 272 + (c & 15) * 16);
        }
        __syncthreads();
#pragma unroll
        for (int i = 0; i < 7; ++i) {
            int c = tid + i * 128;
            if (c < L * 16) {
                int rw = c >> 4, ch = c & 15;
                float s = kn[rw];
                uint32_t h0, l0, h1, l1;
                split_pack(r[i].x * s, r[i].y * s, h0, l0);
                split_pack(r[i].z * s, r[i].w * s, h1, l1);
                *(uint2*)(asm_ + AO_KH + rw * 144 + ch * 8) = make_uint2(h0, h1);
                *(uint2*)(asm_ + AO_KL + rw * 144 + ch * 8) = make_uint2(l0, l1);
            }
        }
        // V
#pragma unroll
        for (int i = 0; i < 7; ++i) {
            int c = tid + i * 128;
            if (c < L * 16) r[i] = *(const float4*)(asm_ + AO_VH + (c >> 4) * 256 + (c & 15) * 16);
        }
        __syncthreads();
#pragma unroll
        for (int i = 0; i < 7; ++i) {
            int c = tid + i * 128;
            if (c < L * 16) {
                int rw = c >> 4, ch = c & 15;
                uint32_t h0, l0, h1, l1;
                split_pack(r[i].x, r[i].y, h0, l0);
                split_pack(r[i].z, r[i].w, h1, l1);
                *(uint2*)(asm_ + AO_VH + rw * 144 + ch * 8) = make_uint2(h0, h1);
                *(uint2*)(asm_ + AO_VL + rw * 144 + ch * 8) = make_uint2(l0, l1);
            }
        }
        // zero V pad rows 49..63 (masked-P * NaN hazard); Q/K pads are benign
        for (int c2 = tid; c2 < 15 * 18; c2 += 128) {
            int rr = c2 / 18, ch = c2 - rr * 18;
            int rw = L + rr;
            *(uint2*)(asm_ + AO_VH + rw * 144 + ch * 8) = make_uint2(0u, 0u);
            *(uint2*)(asm_ + AO_VL + rw * 144 + ch * 8) = make_uint2(0u, 0u);
        }
    }
    __syncthreads();

    // ---- scores: S(64x64) = Qhat @ Khat^T, warp w -> m16 tile w ----
    float sacc[8][4];
#pragma unroll
    for (int nt = 0; nt < 8; ++nt)
#pragma unroll
        for (int e = 0; e < 4; ++e) sacc[nt][e] = 0.0f;

    {
        const uint32_t aq = sbase + AO_QH
            + (uint32_t)((warp * 16 + (lane & 15)) * 144 + (lane >> 4) * 16);
        const uint32_t bk = sbase + AO_KH
            + (uint32_t)(((lane & 7) + ((lane >> 4) << 3)) * 144 + ((lane >> 3) & 1) * 16);
        const uint32_t QLD = AO_QL - AO_QH;
#pragma unroll
        for (int ks = 0; ks < 4; ++ks) {
            uint32_t ah[4], al[4];
            LDSM4(ah, aq + ks * 32);
            LDSM4(al, aq + QLD + ks * 32);
#pragma unroll
            for (int nt2 = 0; nt2 < 4; ++nt2) {
                uint32_t bh[4], bl[4];
                LDSM4(bh, bk + nt2 * (16 * 144) + ks * 32);
                LDSM4(bl, bk + QLD + nt2 * (16 * 144) + ks * 32);
                MMA16816(sacc[2 * nt2],     ah, bh[0], bh[1]);
                MMA16816(sacc[2 * nt2 + 1], ah, bh[2], bh[3]);
                MMA16816(sacc[2 * nt2],     ah, bl[0], bl[1]);
                MMA16816(sacc[2 * nt2 + 1], ah, bl[2], bl[3]);
                MMA16816(sacc[2 * nt2],     al, bh[0], bh[1]);
                MMA16816(sacc[2 * nt2 + 1], al, bh[2], bh[3]);
            }
        }
    }

    // ---- register softmax (rows r=lane>>2, r+8; cols >= 49 masked) ----
    {
        float m0 = -1e30f, m1 = -1e30f;
#pragma unroll
        for (int nt = 0; nt < 8; ++nt) {
            int jb = nt * 8 + (lane & 3) * 2;
            if (jb >= L)     { sacc[nt][0] = -1e30f; sacc[nt][2] = -1e30f; }
            if (jb + 1 >= L) { sacc[nt][1] = -1e30f; sacc[nt][3] = -1e30f; }
            m0 = fmaxf(m0, fmaxf(sacc[nt][0], sacc[nt][1]));
            m1 = fmaxf(m1, fmaxf(sacc[nt][2], sacc[nt][3]));
        }
        m0 = fmaxf(m0, __shfl_xor_sync(0xffffffffu, m0, 1));
        m0 = fmaxf(m0, __shfl_xor_sync(0xffffffffu, m0, 2));
        m1 = fmaxf(m1, __shfl_xor_sync(0xffffffffu, m1, 1));
        m1 = fmaxf(m1, __shfl_xor_sync(0xffffffffu, m1, 2));
        float s0 = 0.0f, s1 = 0.0f;
#pragma unroll
        for (int nt = 0; nt < 8; ++nt) {
            sacc[nt][0] = __expf(sacc[nt][0] - m0); s0 += sacc[nt][0];
            sacc[nt][1] = __expf(sacc[nt][1] - m0); s0 += sacc[nt][1];
            sacc[nt][2] = __expf(sacc[nt][2] - m1); s1 += sacc[nt][2];
            sacc[nt][3] = __expf(sacc[nt][3] - m1); s1 += sacc[nt][3];
        }
        s0 += __shfl_xor_sync(0xffffffffu, s0, 1);
        s0 += __shfl_xor_sync(0xffffffffu, s0, 2);
        s1 += __shfl_xor_sync(0xffffffffu, s1, 1);
        s1 += __shfl_xor_sync(0xffffffffu, s1, 2);
        float i0 = 1.0f / s0, i1 = 1.0f / s1;
#pragma unroll
        for (int nt = 0; nt < 8; ++nt) {
            sacc[nt][0] *= i0; sacc[nt][1] *= i0;
            sacc[nt][2] *= i1; sacc[nt][3] *= i1;
        }
    }

    // ---- O(64x64) = P @ V via mma (P in regs, V via ldmatrix.trans) ----
    float oacc[8][4];
#pragma unroll
    for (int nt = 0; nt < 8; ++nt)
#pragma unroll
        for (int e = 0; e < 4; ++e) oacc[nt][e] = 0.0f;

    {
        const uint32_t bv = sbase + AO_VH
            + (uint32_t)(((lane & 7) + ((lane >> 3) & 1) * 8) * 144 + (lane >> 4) * 16);
        const uint32_t VLD = AO_VL - AO_VH;
#pragma unroll
        for (int jj = 0; jj < 4; ++jj) {
            uint32_t ph[4], pl[4];
            split_pack(sacc[2 * jj][0],     sacc[2 * jj][1],     ph[0], pl[0]);
            split_pack(sacc[2 * jj][2],     sacc[2 * jj][3],     ph[1], pl[1]);
            split_pack(sacc[2 * jj + 1][0], sacc[2 * jj + 1][1], ph[2], pl[2]);
            split_pack(sacc[2 * jj + 1][2], sacc[2 * jj + 1][3], ph[3], pl[3]);
#pragma unroll
            for (int nd2 = 0; nd2 < 4; ++nd2) {
                uint32_t vh[4], vl[4];
                LDSM4T(vh, bv + jj * (16 * 144) + nd2 * 32);
                LDSM4T(vl, bv + VLD + jj * (16 * 144) + nd2 * 32);
                MMA16816(oacc[2 * nd2],     ph, vh[0], vh[1]);
                MMA16816(oacc[2 * nd2 + 1], ph, vh[2], vh[3]);
                MMA16816(oacc[2 * nd2],     ph, vl[0], vl[1]);
                MMA16816(oacc[2 * nd2 + 1], ph, vl[2], vl[3]);
                MMA16816(oacc[2 * nd2],     pl, vh[0], vh[1]);
                MMA16816(oacc[2 * nd2 + 1], pl, vh[2], vh[3]);
            }
        }
    }

    // ---- stage O to fp32 (reuse Q tile region), coalesced bf16 store ----
    __syncthreads();
    {
        int r0 = warp * 16 + (lane >> 2);
#pragma unroll
        for (int nt = 0; nt < 8; ++nt) {
            int d0 = nt * 8 + (lane & 3) * 2;
            if (r0 < L) {
                Qf[r0 * 68 + d0]     = oacc[nt][0];
                Qf[r0 * 68 + d0 + 1] = oacc[nt][1];
            }
            if (r0 + 8 < L) {
                Qf[(r0 + 8) * 68 + d0]     = oacc[nt][2];
                Qf[(r0 + 8) * 68 + d0 + 1] = oacc[nt][3];
            }
        }
    }
    __syncthreads();

    for (int t = warp; t < L; t += 4) {
        size_t o = (size_t)grows[t] * DIM + h * HD;
        float v0 = Qf[t * 68 + lane];
        float v1 = Qf[t * 68 + lane + 32];
        uint16_t h0, l0, h1, l1;
        split1(v0, h0, l0);
        split1(v1, h1, l1);
        atthi[o + lane]      = h0;
        attlo[o + lane]      = l0;
        atthi[o + lane + 32] = h1;
        attlo[o + lane + 32] = l1;
    }
}

// ---------------------------------------------------------------------------
extern "C" void kernel_launch(void* const* d_in, const int* in_sizes, int n_in,
                              void* d_out, int out_size)
{
    const float* x     = (const float*)d_in[0];
    const float* qkv_w = (const float*)d_in[1];
    const float* projw = (const float*)d_in[2];
    float* out = (float*)d_out;

    float *qkv_ptr;
    uint16_t *xhi, *xlo, *qwhi, *qwlo, *pwhi, *pwlo, *atthi, *attlo;
    cudaGetSymbolAddress((void**)&qkv_ptr, g_qkv);
    cudaGetSymbolAddress((void**)&xhi,  g_xhi);
    cudaGetSymbolAddress((void**)&xlo,  g_xlo);
    cudaGetSymbolAddress((void**)&qwhi, g_qwhi);
    cudaGetSymbolAddress((void**)&qwlo, g_qwlo);
    cudaGetSymbolAddress((void**)&pwhi, g_pwhi);
    cudaGetSymbolAddress((void**)&pwlo, g_pwlo);
    cudaGetSymbolAddress((void**)&atthi, g_atthi);
    cudaGetSymbolAddress((void**)&attlo, g_attlo);

    cudaFuncSetAttribute(gemm_presplit_kernel,
                         cudaFuncAttributeMaxDynamicSharedMemorySize, SMEM_GEMM);
    cudaFuncSetAttribute(window_attn_kernel,
                         cudaFuncAttributeMaxDynamicSharedMemorySize, SMEM_ATTN);

    // Launch order: attention is launch #4 (the profiled slot).
    split_kernel<<<1024, 256>>>(x, xhi, xlo, (size_t)TOKENS * DIM / 4, 1);      // 1 (+rope)
    split_kernel<<<64, 256>>>(qkv_w, qwhi, qwlo, (size_t)3 * DIM * DIM / 4, 0); // 2

    // qkv = x @ qkv_w^T                                                        // 3
    gemm_presplit_kernel<<<dim3(3 * DIM / BN, TOKENS / BM), 256, SMEM_GEMM>>>(
        xhi, xlo, qwhi, qwlo, qkv_ptr, TOKENS, 3 * DIM, DIM);

    // windowed attention (tensor-core, compact smem)                          // 4 <-- profiled
    window_attn_kernel<<<dim3(NH, NWIN), 128, SMEM_ATTN>>>(qkv_ptr, atthi, attlo);

    split_kernel<<<32, 256>>>(projw, pwhi, pwlo, (size_t)DIM * DIM / 4, 0);     // 5

    // out = att @ proj_w^T                                                     // 6
    gemm_presplit_kernel<<<dim3(DIM / BN, TOKENS / BM), 256, SMEM_GEMM>>>(
        atthi, attlo, pwhi, pwlo, out, TOKENS, DIM, DIM);
}

// round 16
// speedup vs baseline: 1.5016x; 1.0021x over previous
#include <cuda_runtime.h>
#include <math.h>
#include <stdint.h>

// Problem constants (fixed by setup_inputs)
#define BATCH   2
#define IMG     224
#define TOKENS  (BATCH*IMG*IMG)   // 100352
#define DIM     768
#define NH      12
#define HD      64
#define WS      7
#define L       (WS*WS)           // 49
#define NWIN    (BATCH*(IMG/WS)*(IMG/WS))  // 2048
#define SHIFT   3

// Scratch (device globals: allocation is forbidden in kernel_launch)
__device__ float    g_qkv[(size_t)TOKENS * 3 * DIM];
__device__ uint16_t g_xhi[(size_t)TOKENS * DIM];
__device__ uint16_t g_xlo[(size_t)TOKENS * DIM];
__device__ uint16_t g_qwhi[(size_t)3 * DIM * DIM];
__device__ uint16_t g_qwlo[(size_t)3 * DIM * DIM];
__device__ uint16_t g_pwhi[(size_t)DIM * DIM];
__device__ uint16_t g_pwlo[(size_t)DIM * DIM];
__device__ uint16_t g_atthi[(size_t)TOKENS * DIM];
__device__ uint16_t g_attlo[(size_t)TOKENS * DIM];
__device__ float    g_sin[L * 32];
__device__ float    g_cos[L * 32];

// ============================================================================
// helpers
// ============================================================================
__device__ __forceinline__ uint32_t smem_u32(const void* p) {
    uint32_t a;
    asm("{ .reg .u64 t; cvta.to.shared.u64 t, %1; cvt.u32.u64 %0, t; }" : "=r"(a) : "l"(p));
    return a;
}

__device__ __forceinline__ void split_pack(float x, float y, uint32_t& hi, uint32_t& lo) {
    asm("cvt.rn.bf16x2.f32 %0, %1, %2;" : "=r"(hi) : "f"(y), "f"(x));
    float hx = __uint_as_float(hi << 16);
    float hy = __uint_as_float(hi & 0xffff0000u);
    float lx = x - hx;
    float ly = y - hy;
    asm("cvt.rn.bf16x2.f32 %0, %1, %2;" : "=r"(lo) : "f"(ly), "f"(lx));
}

__device__ __forceinline__ void split1(float x, uint16_t& h, uint16_t& l) {
    uint16_t hh;
    asm("cvt.rn.bf16.f32 %0, %1;" : "=h"(hh) : "f"(x));
    float hf = __uint_as_float(((uint32_t)hh) << 16);
    asm("cvt.rn.bf16.f32 %0, %1;" : "=h"(l) : "f"(x - hf));
    h = hh;
}

#define CPA16(dst, src) \
    asm volatile("cp.async.cg.shared.global [%0], [%1], 16;" :: "r"(dst), "l"(src) : "memory")
#define CPA_COMMIT()  asm volatile("cp.async.commit_group;" ::: "memory")
#define CPA_WAIT2()   asm volatile("cp.async.wait_group 2;" ::: "memory")
#define CPA_WAITALL() asm volatile("cp.async.wait_all;" ::: "memory")

#define LDSM4(r, addr) \
    asm volatile("ldmatrix.sync.aligned.m8n8.x4.shared.b16 {%0,%1,%2,%3}, [%4];" \
        : "=r"((r)[0]), "=r"((r)[1]), "=r"((r)[2]), "=r"((r)[3]) : "r"(addr))

#define LDSM4T(r, addr) \
    asm volatile("ldmatrix.sync.aligned.m8n8.x4.trans.shared.b16 {%0,%1,%2,%3}, [%4];" \
        : "=r"((r)[0]), "=r"((r)[1]), "=r"((r)[2]), "=r"((r)[3]) : "r"(addr))

#define MMA16816(d, a, b0, b1) \
    asm volatile("mma.sync.aligned.m16n8k16.row.col.f32.bf16.bf16.f32 " \
        "{%0,%1,%2,%3},{%4,%5,%6,%7},{%8,%9},{%0,%1,%2,%3};" \
        : "+f"((d)[0]), "+f"((d)[1]), "+f"((d)[2]), "+f"((d)[3]) \
        : "r"((a)[0]), "r"((a)[1]), "r"((a)[2]), "r"((a)[3]), "r"(b0), "r"(b1))

// ============================================================================
// fp32 -> bf16 hi/lo split pre-pass (optionally also builds RoPE tables)
// ============================================================================
__global__ void split_kernel(const float* __restrict__ src,
                             uint16_t* __restrict__ hi, uint16_t* __restrict__ lo,
                             size_t n4, int do_rope)
{
    if (do_rope && blockIdx.x == 0) {
        for (int i = threadIdx.x; i < L * 32; i += blockDim.x) {
            int tok = i >> 5, d = i & 31;
            int ty = tok / WS, tx = tok - ty * WS;
            int f = d & 15;
            float inv = powf(100.0f, -((float)f) / 16.0f);
            float ang = ((d < 16) ? (float)ty : (float)tx) * inv;
            g_sin[i] = sinf(ang);
            g_cos[i] = cosf(ang);
        }
    }
    size_t idx = (size_t)blockIdx.x * blockDim.x + threadIdx.x;
    size_t stride = (size_t)gridDim.x * blockDim.x;
    for (; idx < n4; idx += stride) {
        float4 v = ((const float4*)src)[idx];
        uint32_t h0, l0, h1, l1;
        split_pack(v.x, v.y, h0, l0);
        split_pack(v.z, v.w, h1, l1);
        ((uint2*)hi)[idx] = make_uint2(h0, h1);
        ((uint2*)lo)[idx] = make_uint2(l0, l1);
    }
}

// ============================================================================
// 3x-BF16-split GEMM (R8/R13 configuration — empirical best):
// CTA tile 128x128, BK=16, 256 threads (8 warps, 4m x 2n), 4-stage, 2 CTA/SM.
// ============================================================================
#define BM 128
#define BN 128
#define BK 16
#define PADB 48
#define A_LO  6144u
#define B_HI  12288u
#define B_LO  18432u
#define BUF_B 24576u
#define SMEM_GEMM (4u * BUF_B)   // 98304

__global__ __launch_bounds__(256, 2) void gemm_presplit_kernel(
    const uint16_t* __restrict__ Ahi, const uint16_t* __restrict__ Alo,
    const uint16_t* __restrict__ Bhi, const uint16_t* __restrict__ Blo,
    float* __restrict__ C, int M, int N, int K)
{
    extern __shared__ char smem[];
    const uint32_t sb = smem_u32(smem);
    const int tid  = threadIdx.x;
    const int lane = tid & 31;
    const int wid  = tid >> 5;
    const int mtile = blockIdx.y, ntile = blockIdx.x;
    const int rm = (wid & 3) * 32;
    const int nb = (wid >> 2) * 64;

    const int row = tid >> 1, half = tid & 1;
    const uint16_t* pAhi = Ahi + (size_t)(mtile * BM + row) * K + half * 8;
    const uint16_t* pAlo = Alo + (size_t)(mtile * BM + row) * K + half * 8;
    const uint16_t* pBhi = Bhi + (size_t)(ntile * BN + row) * K + half * 8;
    const uint16_t* pBlo = Blo + (size_t)(ntile * BN + row) * K + half * 8;

    const uint32_t dA = sb + (uint32_t)(row * PADB + half * 16);
    const uint32_t dB = sb + B_HI + (uint32_t)(row * PADB + half * 16);

    auto issue = [&](int s) {
        const uint32_t off = (uint32_t)(s & 3) * BUF_B;
        const int k0 = s * BK;
        CPA16(dA + off,                 pAhi + k0);
        CPA16(dA + off + A_LO,          pAlo + k0);
        CPA16(dB + off,                 pBhi + k0);
        CPA16(dB + off + (B_LO - B_HI), pBlo + k0);
        CPA_COMMIT();
    };

    float acc[2][8][4];
#pragma unroll
    for (int mt = 0; mt < 2; ++mt)
#pragma unroll
        for (int nt = 0; nt < 8; ++nt)
#pragma unroll
            for (int e = 0; e < 4; ++e) acc[mt][nt][e] = 0.0f;

    const uint32_t a_l = sb + (uint32_t)((rm + (lane & 15)) * PADB + (lane >> 4) * 16);
    const uint32_t b_l = sb + B_HI + (uint32_t)((nb + (lane & 7) + ((lane >> 4) << 3)) * PADB
                                                + ((lane >> 3) & 1) * 16);

    const int NIT = K / BK;
    issue(0); issue(1); issue(2);

    for (int it = 0; it < NIT; ++it) {
        CPA_WAIT2();
        __syncthreads();
        const uint32_t so = (uint32_t)(it & 3) * BUF_B;

        uint32_t ah[2][4], al[2][4];
#pragma unroll
        for (int mt = 0; mt < 2; ++mt) {
            LDSM4(ah[mt], a_l + so + mt * (16 * PADB));
            LDSM4(al[mt], a_l + so + A_LO + mt * (16 * PADB));
        }

#pragma unroll
        for (int hf = 0; hf < 2; ++hf) {
            uint32_t bh[2][4], bl[2][4];
#pragma unroll
            for (int q = 0; q < 2; ++q) {
                const int nt2 = hf * 2 + q;
                LDSM4(bh[q], b_l + so + nt2 * (16 * PADB));
                LDSM4(bl[q], b_l + so + (B_LO - B_HI) + nt2 * (16 * PADB));
            }
#pragma unroll
            for (int mt = 0; mt < 2; ++mt)
#pragma unroll
                for (int q = 0; q < 2; ++q) {
                    MMA16816(acc[mt][hf * 4 + 2 * q],     ah[mt], bh[q][0], bh[q][1]);
                    MMA16816(acc[mt][hf * 4 + 2 * q + 1], ah[mt], bh[q][2], bh[q][3]);
                }
#pragma unroll
            for (int mt = 0; mt < 2; ++mt)
#pragma unroll
                for (int q = 0; q < 2; ++q) {
                    MMA16816(acc[mt][hf * 4 + 2 * q],     ah[mt], bl[q][0], bl[q][1]);
                    MMA16816(acc[mt][hf * 4 + 2 * q + 1], ah[mt], bl[q][2], bl[q][3]);
                }
#pragma unroll
            for (int mt = 0; mt < 2; ++mt)
#pragma unroll
                for (int q = 0; q < 2; ++q) {
                    MMA16816(acc[mt][hf * 4 + 2 * q],     al[mt], bh[q][0], bh[q][1]);
                    MMA16816(acc[mt][hf * 4 + 2 * q + 1], al[mt], bh[q][2], bh[q][3]);
                }
        }

        if (it + 3 < NIT) issue(it + 3);
        else CPA_COMMIT();
    }

    const int rowb = mtile * BM + rm + (lane >> 2);
    const int colb = ntile * BN + nb + (lane & 3) * 2;
#pragma unroll
    for (int mt = 0; mt < 2; ++mt) {
#pragma unroll
        for (int nt = 0; nt < 8; ++nt) {
            float* p = C + (size_t)(rowb + mt * 16) * N + colb + nt * 8;
            *(float2*)p                   = make_float2(acc[mt][nt][0], acc[mt][nt][1]);
            *(float2*)(p + 8 * (size_t)N) = make_float2(acc[mt][nt][2], acc[mt][nt][3]);
        }
    }
}

// ============================================================================
// Window attention v5 (tensor-core, compact smem, reordered MMAs, direct
// register->gmem O store): 128 threads, 4 CTAs/SM.
// ============================================================================
#define AO_GROWS 0
#define AO_QN    256
#define AO_KN    512
#define AO_QH    768u
#define AO_QL    (AO_QH + 9216u)
#define AO_KH    (AO_QL + 9216u)
#define AO_KL    (AO_KH + 9216u)
#define AO_VH    (AO_KL + 9216u)
#define AO_VL    (AO_VH + 9216u)
#define SMEM_ATTN (AO_VL + 9216u)   // 56064

__global__ __launch_bounds__(128, 4) void window_attn_kernel(
    const float* __restrict__ qkv,
    uint16_t* __restrict__ atthi, uint16_t* __restrict__ attlo)
{
    extern __shared__ char asm_[];
    const uint32_t sbase = smem_u32(asm_);
    int*   grows = (int*)(asm_ + AO_GROWS);
    float* qn    = (float*)(asm_ + AO_QN);
    float* kn    = (float*)(asm_ + AO_KN);
    float* Qf    = (float*)(asm_ + AO_QH);   // fp32 staging aliases (stride 68)
    float* Kf    = (float*)(asm_ + AO_KH);

    const int h   = blockIdx.x;
    const int w   = blockIdx.y;
    const int tid = threadIdx.x;
    const int lane = tid & 31;
    const int warp = tid >> 5;
    const int b   = w >> 10;
    const int rem = w & 1023;
    const int wh  = rem >> 5, ww = rem & 31;

    if (tid < L) {
        int ty = tid / WS, tx = tid - ty * WS;
        int y = wh * WS + ty + SHIFT; if (y >= IMG) y -= IMG;
        int x = ww * WS + tx + SHIFT; if (x >= IMG) x -= IMG;
        grows[tid] = b * (IMG * IMG) + y * IMG + x;
    }
    __syncthreads();

    // ---- bulk gather: fp32 rows into tile-region aliases ----
    for (int c = tid; c < L * 16; c += 128) {
        int rw = c >> 4, ch = c & 15;
        const float* base = qkv + (size_t)grows[rw] * (3 * DIM) + h * HD + ch * 4;
        CPA16(sbase + AO_QH + rw * 272 + ch * 16, base);
        CPA16(sbase + AO_KH + rw * 272 + ch * 16, base + DIM);
        CPA16(sbase + AO_VH + rw * 256 + ch * 16, base + 2 * DIM);
    }
    CPA_COMMIT();
    CPA_WAITALL();
    __syncthreads();

    // ---- RoPE in place (q and k, fp32) ----
    for (int r = warp; r < 2 * L; r += 4) {
        float* T = (r < L) ? Qf : Kf;
        int rw = (r < L) ? r : r - L;
        float t1 = T[rw * 68 + lane];
        float t2 = T[rw * 68 + 32 + lane];
        float s = g_sin[rw * 32 + lane];
        float c = g_cos[rw * 32 + lane];
        T[rw * 68 + lane]      = t1 * c - t2 * s;
        T[rw * 68 + 32 + lane] = t1 * s + t2 * c;
    }
    __syncthreads();

    // ---- norms: qn = 1/|q|, kn = 100/|k| ----
    if (tid < L) {
        float ssq = 0.0f;
#pragma unroll
        for (int d4 = 0; d4 < 16; ++d4) {
            float4 v = *(const float4*)&Kf[tid * 68 + d4 * 4];
            ssq += v.x * v.x + v.y * v.y + v.z * v.z + v.w * v.w;
        }
        kn[tid] = 100.0f / fmaxf(sqrtf(ssq), 1e-12f);
    } else if (tid >= 64 && tid < 64 + L) {
        int i = tid - 64;
        float ssq = 0.0f;
#pragma unroll
        for (int d4 = 0; d4 < 16; ++d4) {
            float4 v = *(const float4*)&Qf[i * 68 + d4 * 4];
            ssq += v.x * v.x + v.y * v.y + v.z * v.z + v.w * v.w;
        }
        qn[i] = 1.0f / fmaxf(sqrtf(ssq), 1e-12f);
    }
    __syncthreads();

    // ---- in-place conversion to scaled bf16 hi/lo (register staging) ----
    {
        float4 r[7];
        // Q
#pragma unroll
        for (int i = 0; i < 7; ++i) {
            int c = tid + i * 128;
            if (c < L * 16) r[i] = *(const float4*)(asm_ + AO_QH + (c >> 4) * 272 + (c & 15) * 16);
        }
        __syncthreads();
#pragma unroll
        for (int i = 0; i < 7; ++i) {
            int c = tid + i * 128;
            if (c < L * 16) {
                int rw = c >> 4, ch = c & 15;
                float s = qn[rw];
                uint32_t h0, l0, h1, l1;
                split_pack(r[i].x * s, r[i].y * s, h0, l0);
                split_pack(r[i].z * s, r[i].w * s, h1, l1);
                *(uint2*)(asm_ + AO_QH + rw * 144 + ch * 8) = make_uint2(h0, h1);
                *(uint2*)(asm_ + AO_QL + rw * 144 + ch * 8) = make_uint2(l0, l1);
            }
        }
        // K
#pragma unroll
        for (int i = 0; i < 7; ++i) {
            int c = tid + i * 128;
            if (c < L * 16) r[i] = *(const float4*)(asm_ + AO_KH + (c >> 4) * 272 + (c & 15) * 16);
        }
        __syncthreads();
#pragma unroll
        for (int i = 0; i < 7; ++i) {
            int c = tid + i * 128;
            if (c < L * 16) {
                int rw = c >> 4, ch = c & 15;
                float s = kn[rw];
                uint32_t h0, l0, h1, l1;
                split_pack(r[i].x * s, r[i].y * s, h0, l0);
                split_pack(r[i].z * s, r[i].w * s, h1, l1);
                *(uint2*)(asm_ + AO_KH + rw * 144 + ch * 8) = make_uint2(h0, h1);
                *(uint2*)(asm_ + AO_KL + rw * 144 + ch * 8) = make_uint2(l0, l1);
            }
        }
        // V
#pragma unroll
        for (int i = 0; i < 7; ++i) {
            int c = tid + i * 128;
            if (c < L * 16) r[i] = *(const float4*)(asm_ + AO_VH + (c >> 4) * 256 + (c & 15) * 16);
        }
        __syncthreads();
#pragma unroll
        for (int i = 0; i < 7; ++i) {
            int c = tid + i * 128;
            if (c < L * 16) {
                int rw = c >> 4, ch = c & 15;
                uint32_t h0, l0, h1, l1;
                split_pack(r[i].x, r[i].y, h0, l0);
                split_pack(r[i].z, r[i].w, h1, l1);
                *(uint2*)(asm_ + AO_VH + rw * 144 + ch * 8) = make_uint2(h0, h1);
                *(uint2*)(asm_ + AO_VL + rw * 144 + ch * 8) = make_uint2(l0, l1);
            }
        }
        // zero V pad rows 49..63; Q/K pad garbage is provably benign
        for (int c2 = tid; c2 < 15 * 18; c2 += 128) {
            int rr = c2 / 18, ch = c2 - rr * 18;
            int rw = L + rr;
            *(uint2*)(asm_ + AO_VH + rw * 144 + ch * 8) = make_uint2(0u, 0u);
            *(uint2*)(asm_ + AO_VL + rw * 144 + ch * 8) = make_uint2(0u, 0u);
        }
    }
    __syncthreads();

    // ---- scores: S(64x64) = Qhat @ Khat^T (term-major, acc distance 4) ----
    float sacc[8][4];
#pragma unroll
    for (int nt = 0; nt < 8; ++nt)
#pragma unroll
        for (int e = 0; e < 4; ++e) sacc[nt][e] = 0.0f;

    {
        const uint32_t aq = sbase + AO_QH
            + (uint32_t)((warp * 16 + (lane & 15)) * 144 + (lane >> 4) * 16);
        const uint32_t bk = sbase + AO_KH
            + (uint32_t)(((lane & 7) + ((lane >> 4) << 3)) * 144 + ((lane >> 3) & 1) * 16);
        const uint32_t QLD = AO_QL - AO_QH;
#pragma unroll
        for (int ks = 0; ks < 4; ++ks) {
            uint32_t ah[4], al[4];
            LDSM4(ah, aq + ks * 32);
            LDSM4(al, aq + QLD + ks * 32);
#pragma unroll
            for (int hf = 0; hf < 2; ++hf) {
                uint32_t bh[2][4], bl[2][4];
#pragma unroll
                for (int q = 0; q < 2; ++q) {
                    const int nt2 = hf * 2 + q;
                    LDSM4(bh[q], bk + nt2 * (16 * 144) + ks * 32);
                    LDSM4(bl[q], bk + QLD + nt2 * (16 * 144) + ks * 32);
                }
#pragma unroll
                for (int q = 0; q < 2; ++q) {
                    MMA16816(sacc[(hf * 2 + q) * 2],     ah, bh[q][0], bh[q][1]);
                    MMA16816(sacc[(hf * 2 + q) * 2 + 1], ah, bh[q][2], bh[q][3]);
                }
#pragma unroll
                for (int q = 0; q < 2; ++q) {
                    MMA16816(sacc[(hf * 2 + q) * 2],     ah, bl[q][0], bl[q][1]);
                    MMA16816(sacc[(hf * 2 + q) * 2 + 1], ah, bl[q][2], bl[q][3]);
                }
#pragma unroll
                for (int q = 0; q < 2; ++q) {
                    MMA16816(sacc[(hf * 2 + q) * 2],     al, bh[q][0], bh[q][1]);
                    MMA16816(sacc[(hf * 2 + q) * 2 + 1], al, bh[q][2], bh[q][3]);
                }
            }
        }
    }

    // ---- register softmax (rows r=lane>>2, r+8; cols >= 49 masked) ----
    {
        float m0 = -1e30f, m1 = -1e30f;
#pragma unroll
        for (int nt = 0; nt < 8; ++nt) {
            int jb = nt * 8 + (lane & 3) * 2;
            if (jb >= L)     { sacc[nt][0] = -1e30f; sacc[nt][2] = -1e30f; }
            if (jb + 1 >= L) { sacc[nt][1] = -1e30f; sacc[nt][3] = -1e30f; }
            m0 = fmaxf(m0, fmaxf(sacc[nt][0], sacc[nt][1]));
            m1 = fmaxf(m1, fmaxf(sacc[nt][2], sacc[nt][3]));
        }
        m0 = fmaxf(m0, __shfl_xor_sync(0xffffffffu, m0, 1));
        m0 = fmaxf(m0, __shfl_xor_sync(0xffffffffu, m0, 2));
        m1 = fmaxf(m1, __shfl_xor_sync(0xffffffffu, m1, 1));
        m1 = fmaxf(m1, __shfl_xor_sync(0xffffffffu, m1, 2));
        float s0 = 0.0f, s1 = 0.0f;
#pragma unroll
        for (int nt = 0; nt < 8; ++nt) {
            sacc[nt][0] = __expf(sacc[nt][0] - m0); s0 += sacc[nt][0];
            sacc[nt][1] = __expf(sacc[nt][1] - m0); s0 += sacc[nt][1];
            sacc[nt][2] = __expf(sacc[nt][2] - m1); s1 += sacc[nt][2];
            sacc[nt][3] = __expf(sacc[nt][3] - m1); s1 += sacc[nt][3];
        }
        s0 += __shfl_xor_sync(0xffffffffu, s0, 1);
        s0 += __shfl_xor_sync(0xffffffffu, s0, 2);
        s1 += __shfl_xor_sync(0xffffffffu, s1, 1);
        s1 += __shfl_xor_sync(0xffffffffu, s1, 2);
        float i0 = 1.0f / s0, i1 = 1.0f / s1;
#pragma unroll
        for (int nt = 0; nt < 8; ++nt) {
            sacc[nt][0] *= i0; sacc[nt][1] *= i0;
            sacc[nt][2] *= i1; sacc[nt][3] *= i1;
        }
    }

    // ---- O(64x64) = P @ V via mma (term-major, acc distance 4) ----
    float oacc[8][4];
#pragma unroll
    for (int nt = 0; nt < 8; ++nt)
#pragma unroll
        for (int e = 0; e < 4; ++e) oacc[nt][e] = 0.0f;

    {
        const uint32_t bv = sbase + AO_VH
            + (uint32_t)(((lane & 7) + ((lane >> 3) & 1) * 8) * 144 + (lane >> 4) * 16);
        const uint32_t VLD = AO_VL - AO_VH;
#pragma unroll
        for (int jj = 0; jj < 4; ++jj) {
            uint32_t ph[4], pl[4];
            split_pack(sacc[2 * jj][0],     sacc[2 * jj][1],     ph[0], pl[0]);
            split_pack(sacc[2 * jj][2],     sacc[2 * jj][3],     ph[1], pl[1]);
            split_pack(sacc[2 * jj + 1][0], sacc[2 * jj + 1][1], ph[2], pl[2]);
            split_pack(sacc[2 * jj + 1][2], sacc[2 * jj + 1][3], ph[3], pl[3]);
#pragma unroll
            for (int hf = 0; hf < 2; ++hf) {
                uint32_t vh[2][4], vl[2][4];
#pragma unroll
                for (int q = 0; q < 2; ++q) {
                    const int nd2 = hf * 2 + q;
                    LDSM4T(vh[q], bv + jj * (16 * 144) + nd2 * 32);
                    LDSM4T(vl[q], bv + VLD + jj * (16 * 144) + nd2 * 32);
                }
#pragma unroll
                for (int q = 0; q < 2; ++q) {
                    MMA16816(oacc[(hf * 2 + q) * 2],     ph, vh[q][0], vh[q][1]);
                    MMA16816(oacc[(hf * 2 + q) * 2 + 1], ph, vh[q][2], vh[q][3]);
                }
#pragma unroll
                for (int q = 0; q < 2; ++q) {
                    MMA16816(oacc[(hf * 2 + q) * 2],     ph, vl[q][0], vl[q][1]);
                    MMA16816(oacc[(hf * 2 + q) * 2 + 1], ph, vl[q][2], vl[q][3]);
                }
#pragma unroll
                for (int q = 0; q < 2; ++q) {
                    MMA16816(oacc[(hf * 2 + q) * 2],     pl, vh[q][0], vh[q][1]);
                    MMA16816(oacc[(hf * 2 + q) * 2 + 1], pl, vh[q][2], vh[q][3]);
                }
            }
        }
    }

    // ---- direct register -> gmem O store (bf16 hi/lo, packed u32) ----
    {
        const int r0 = warp * 16 + (lane >> 2);
        const int r1 = r0 + 8;
        const bool ok0 = r0 < L, ok1 = r1 < L;
        size_t o0 = 0, o1 = 0;
        if (ok0) o0 = (size_t)grows[r0] * DIM + h * HD;
        if (ok1) o1 = (size_t)grows[r1] * DIM + h * HD;
#pragma unroll
        for (int nt = 0; nt < 8; ++nt) {
            const int d0 = nt * 8 + (lane & 3) * 2;
            if (ok0) {
                uint16_t h0, l0, h1, l1;
                split1(oacc[nt][0], h0, l0);
                split1(oacc[nt][1], h1, l1);
                *(uint32_t*)(atthi + o0 + d0) = (uint32_t)h0 | ((uint32_t)h1 << 16);
                *(uint32_t*)(attlo + o0 + d0) = (uint32_t)l0 | ((uint32_t)l1 << 16);
            }
            if (ok1) {
                uint16_t h0, l0, h1, l1;
                split1(oacc[nt][2], h0, l0);
                split1(oacc[nt][3], h1, l1);
                *(uint32_t*)(atthi + o1 + d0) = (uint32_t)h0 | ((uint32_t)h1 << 16);
                *(uint32_t*)(attlo + o1 + d0) = (uint32_t)l0 | ((uint32_t)l1 << 16);
            }
        }
    }
}

// ---------------------------------------------------------------------------
extern "C" void kernel_launch(void* const* d_in, const int* in_sizes, int n_in,
                              void* d_out, int out_size)
{
    const float* x     = (const float*)d_in[0];
    const float* qkv_w = (const float*)d_in[1];
    const float* projw = (const float*)d_in[2];
    float* out = (float*)d_out;

    float *qkv_ptr;
    uint16_t *xhi, *xlo, *qwhi, *qwlo, *pwhi, *pwlo, *atthi, *attlo;
    cudaGetSymbolAddress((void**)&qkv_ptr, g_qkv);
    cudaGetSymbolAddress((void**)&xhi,  g_xhi);
    cudaGetSymbolAddress((void**)&xlo,  g_xlo);
    cudaGetSymbolAddress((void**)&qwhi, g_qwhi);
    cudaGetSymbolAddress((void**)&qwlo, g_qwlo);
    cudaGetSymbolAddress((void**)&pwhi, g_pwhi);
    cudaGetSymbolAddress((void**)&pwlo, g_pwlo);
    cudaGetSymbolAddress((void**)&atthi, g_atthi);
    cudaGetSymbolAddress((void**)&attlo, g_attlo);

    cudaFuncSetAttribute(gemm_presplit_kernel,
                         cudaFuncAttributeMaxDynamicSharedMemorySize, SMEM_GEMM);
    cudaFuncSetAttribute(window_attn_kernel,
                         cudaFuncAttributeMaxDynamicSharedMemorySize, SMEM_ATTN);

    // Launch order: attention is launch #4 (the profiled slot).
    split_kernel<<<1024, 256>>>(x, xhi, xlo, (size_t)TOKENS * DIM / 4, 1);      // 1 (+rope)
    split_kernel<<<64, 256>>>(qkv_w, qwhi, qwlo, (size_t)3 * DIM * DIM / 4, 0); // 2

    // qkv = x @ qkv_w^T                                                        // 3
    gemm_presplit_kernel<<<dim3(3 * DIM / BN, TOKENS / BM), 256, SMEM_GEMM>>>(
        xhi, xlo, qwhi, qwlo, qkv_ptr, TOKENS, 3 * DIM, DIM);

    // windowed attention (tensor-core, v5)                                    // 4 <-- profiled
    window_attn_kernel<<<dim3(NH, NWIN), 128, SMEM_ATTN>>>(qkv_ptr, atthi, attlo);

    split_kernel<<<32, 256>>>(projw, pwhi, pwlo, (size_t)DIM * DIM / 4, 0);     // 5

    // out = att @ proj_w^T                                                     // 6
    gemm_presplit_kernel<<<dim3(DIM / BN, TOKENS / BM), 256, SMEM_GEMM>>>(
        atthi, attlo, pwhi, pwlo, out, TOKENS, DIM, DIM);
}